// round 1
// baseline (speedup 1.0000x reference)
#include <cuda_runtime.h>
#include <cstddef>

// ---------------------------------------------------------------------------
// LatentAttention: B=2, T=2048, n_embd=1024, heads=16, latent=64, head_dim=64
//
// Pipeline (M = B*T = 4096 rows):
//   Wqc = per-head (Wq @ Wc)  [precomputed once per launch, 1024x1024]
//   qc  = x @ Wqc + bqc       [4096,1024]   (fuses q projection + compression)
//   k   = x @ Wk  + bk        [4096,1024]
//   v   = x @ Wv  + bv        [4096,1024]
//   y   = causal flash-attention per (b,h) over latent dim 64
//   out = y @ Wo + bo         [4096,1024]
// All fp32 (round 1: establish correctness + profile; tensor cores next).
// ---------------------------------------------------------------------------

#define N_EMBD   1024
#define N_HEADS  16
#define LATENT   64
#define BATCH    2
#define SEQ      2048
#define MROWS    (BATCH * SEQ)          // 4096
#define ATT_SCALE 0.125f                 // 1/sqrt(64)

// ------------------------- device scratch (no cudaMalloc allowed) ----------
__device__ float g_Wqc[N_EMBD * N_EMBD];
__device__ float g_bqc[N_EMBD];
__device__ float g_qc [MROWS * N_EMBD];
__device__ float g_k  [MROWS * N_EMBD];
__device__ float g_v  [MROWS * N_EMBD];
__device__ float g_y  [MROWS * N_EMBD];

// ---------------------------------------------------------------------------
// Precompute Wqc[c, h*64+l] = sum_d Wq[c, h*64+d] * Wc[d, l]
//            bqc[h*64+l]    = sum_d bq[h*64+d]    * Wc[d, l]
// grid: 4096 blocks x 256 threads = 1M threads (one per output element)
// ---------------------------------------------------------------------------
__global__ void build_wqc(const float* __restrict__ Wq,
                          const float* __restrict__ Wc,
                          const float* __restrict__ bq,
                          float* __restrict__ Wqc,
                          float* __restrict__ bqc)
{
    int idx = blockIdx.x * blockDim.x + threadIdx.x;   // 0 .. 1024*1024-1
    int c   = idx >> 10;
    int col = idx & 1023;
    int h   = col >> 6;
    int l   = col & 63;
    const float* wrow = &Wq[(size_t)c * N_EMBD + h * LATENT];
    float s = 0.f;
#pragma unroll 8
    for (int d = 0; d < LATENT; d++)
        s += wrow[d] * Wc[d * LATENT + l];
    Wqc[idx] = s;
    if (c == 0) {
        float sb = 0.f;
#pragma unroll 8
        for (int d = 0; d < LATENT; d++)
            sb += bq[h * LATENT + d] * Wc[d * LATENT + l];
        bqc[col] = sb;
    }
}

// ---------------------------------------------------------------------------
// C[M,N] = A[M,K] @ W[K,N] + bias[N]      (row-major everywhere)
// Tile: 128(M) x 64(N) x 16(K), 256 threads, 8x4 per-thread microtile.
// M,N,K assumed multiples of 128/64/16 (they are: 4096/1024/1024).
// ---------------------------------------------------------------------------
__global__ __launch_bounds__(256)
void gemm_bias(const float* __restrict__ A,
               const float* __restrict__ W,
               const float* __restrict__ bias,
               float* __restrict__ C,
               int M, int N, int K)
{
    __shared__ float As[16][132];   // transposed: As[k][m], +4 pad
    __shared__ float Bs[16][68];    // Bs[k][n], +4 pad

    const int tid = threadIdx.x;
    const int tx  = tid & 15;       // 16 column groups  (4 cols each)
    const int ty  = tid >> 4;       // 16 row groups     (8 rows each)
    const int m0  = blockIdx.y * 128;
    const int n0  = blockIdx.x * 64;

    float acc[8][4];
#pragma unroll
    for (int i = 0; i < 8; i++)
#pragma unroll
        for (int j = 0; j < 4; j++) acc[i][j] = 0.f;

    for (int k0 = 0; k0 < K; k0 += 16) {
        // load A tile: 128 rows x 16 k -> 512 float4, 2 per thread, transpose
#pragma unroll
        for (int i = 0; i < 2; i++) {
            int q   = tid + i * 256;        // 0..511
            int row = q >> 2;               // 0..127
            int kk  = (q & 3) << 2;         // 0,4,8,12
            const float4 a = *reinterpret_cast<const float4*>(
                &A[(size_t)(m0 + row) * K + k0 + kk]);
            As[kk + 0][row] = a.x;
            As[kk + 1][row] = a.y;
            As[kk + 2][row] = a.z;
            As[kk + 3][row] = a.w;
        }
        // load B tile: 16 k x 64 n -> 256 float4, 1 per thread
        {
            int row = tid >> 4;             // 0..15
            int col = (tid & 15) << 2;      // 0..60
            *reinterpret_cast<float4*>(&Bs[row][col]) =
                *reinterpret_cast<const float4*>(
                    &W[(size_t)(k0 + row) * N + n0 + col]);
        }
        __syncthreads();

#pragma unroll
        for (int kk = 0; kk < 16; kk++) {
            const float4 a0 = *reinterpret_cast<const float4*>(&As[kk][ty * 8]);
            const float4 a1 = *reinterpret_cast<const float4*>(&As[kk][ty * 8 + 4]);
            const float4 b  = *reinterpret_cast<const float4*>(&Bs[kk][tx * 4]);
            const float av[8] = {a0.x, a0.y, a0.z, a0.w, a1.x, a1.y, a1.z, a1.w};
            const float bv[4] = {b.x, b.y, b.z, b.w};
#pragma unroll
            for (int i = 0; i < 8; i++)
#pragma unroll
                for (int j = 0; j < 4; j++)
                    acc[i][j] += av[i] * bv[j];
        }
        __syncthreads();
    }

    const float4 bb = *reinterpret_cast<const float4*>(&bias[n0 + tx * 4]);
    const float bvv[4] = {bb.x, bb.y, bb.z, bb.w};
#pragma unroll
    for (int i = 0; i < 8; i++) {
        float4 o = make_float4(acc[i][0] + bvv[0], acc[i][1] + bvv[1],
                               acc[i][2] + bvv[2], acc[i][3] + bvv[3]);
        *reinterpret_cast<float4*>(
            &C[(size_t)(m0 + ty * 8 + i) * N + n0 + tx * 4]) = o;
    }
}

// ---------------------------------------------------------------------------
// Causal flash attention, one block per (q-tile of 64 rows, b*h).
// Layouts in smem (FP=68 padded stride, float4-aligned, conflict-free reads):
//   Qs[lat][row], Ks[lat][key]  -> S = Q.K^T inner loop over lat, float4 loads
//   Vs[key][lat], Ps[row][key]  -> O += P.V  inner loop over key
// Per-thread state: 4x4 tile of S/P and of O; online softmax m/l per row.
// ---------------------------------------------------------------------------
#define FP 68
#define FLASH_SMEM (4 * 64 * FP * (int)sizeof(float))   // 69632 B

__global__ __launch_bounds__(256)
void flash_attn(const float* __restrict__ Qg,
                const float* __restrict__ Kg,
                const float* __restrict__ Vg,
                float* __restrict__ Yg)
{
    extern __shared__ float sm[];
    float* Qs = sm;                  // [64][FP]  (lat-major)
    float* Ks = Qs + 64 * FP;        // [64][FP]  (lat-major)
    float* Vs = Ks + 64 * FP;        // [64][FP]  (key-major)
    float* Ps = Vs + 64 * FP;        // [64][FP]  (row-major)

    const int tid = threadIdx.x;
    const int tx  = tid & 15;        // key/lat column group (4 each)
    const int ty  = tid >> 4;        // query row group (4 each)
    const int qb  = blockIdx.x;      // q tile (0..31)
    const int bh  = blockIdx.y;      // 0..31
    const int b   = bh >> 4;
    const int h   = bh & 15;
    const size_t base = (size_t)b * SEQ * N_EMBD + (size_t)h * LATENT;

    // load Q tile (64 rows x 64 lat), stored transposed Qs[lat][row]
#pragma unroll
    for (int i = 0; i < 4; i++) {
        int q   = tid + i * 256;       // 0..1023
        int row = q >> 4;              // 0..63
        int lat = (q & 15) << 2;       // 0..60
        const float4 v4 = *reinterpret_cast<const float4*>(
            &Qg[base + (size_t)(qb * 64 + row) * N_EMBD + lat]);
        Qs[(lat + 0) * FP + row] = v4.x;
        Qs[(lat + 1) * FP + row] = v4.y;
        Qs[(lat + 2) * FP + row] = v4.z;
        Qs[(lat + 3) * FP + row] = v4.w;
    }

    float m_i[4], l_i[4], O[4][4];
#pragma unroll
    for (int i = 0; i < 4; i++) {
        m_i[i] = -1e30f;
        l_i[i] = 0.f;
#pragma unroll
        for (int j = 0; j < 4; j++) O[i][j] = 0.f;
    }

    for (int jb = 0; jb <= qb; jb++) {
        __syncthreads();   // previous tile's PV reads done; Q load visible
        // load K (transposed) and V (natural) tiles
#pragma unroll
        for (int i = 0; i < 4; i++) {
            int q   = tid + i * 256;
            int key = q >> 4;
            int lat = (q & 15) << 2;
            const size_t goff = base + (size_t)(jb * 64 + key) * N_EMBD + lat;
            const float4 kv = *reinterpret_cast<const float4*>(&Kg[goff]);
            Ks[(lat + 0) * FP + key] = kv.x;
            Ks[(lat + 1) * FP + key] = kv.y;
            Ks[(lat + 2) * FP + key] = kv.z;
            Ks[(lat + 3) * FP + key] = kv.w;
            const float4 vv = *reinterpret_cast<const float4*>(&Vg[goff]);
            *reinterpret_cast<float4*>(&Vs[key * FP + lat]) = vv;
        }
        __syncthreads();

        // S = (Q . K^T) * scale, 4x4 per thread
        float S[4][4];
#pragma unroll
        for (int i = 0; i < 4; i++)
#pragma unroll
            for (int j = 0; j < 4; j++) S[i][j] = 0.f;

#pragma unroll 8
        for (int kk = 0; kk < 64; kk++) {
            const float4 q4 = *reinterpret_cast<const float4*>(&Qs[kk * FP + ty * 4]);
            const float4 k4 = *reinterpret_cast<const float4*>(&Ks[kk * FP + tx * 4]);
            const float qv[4] = {q4.x, q4.y, q4.z, q4.w};
            const float kv[4] = {k4.x, k4.y, k4.z, k4.w};
#pragma unroll
            for (int i = 0; i < 4; i++)
#pragma unroll
                for (int j = 0; j < 4; j++)
                    S[i][j] += qv[i] * kv[j];
        }
#pragma unroll
        for (int i = 0; i < 4; i++)
#pragma unroll
            for (int j = 0; j < 4; j++) S[i][j] *= ATT_SCALE;

        if (jb == qb) {   // causal mask on diagonal tile
#pragma unroll
            for (int i = 0; i < 4; i++)
#pragma unroll
                for (int j = 0; j < 4; j++)
                    if (tx * 4 + j > ty * 4 + i) S[i][j] = -1e30f;
        }

        // online softmax: row max (reduce across tx lanes), exp, row sum
        float mnew[4], alpha[4], rs[4];
#pragma unroll
        for (int i = 0; i < 4; i++) {
            float mx = fmaxf(fmaxf(S[i][0], S[i][1]), fmaxf(S[i][2], S[i][3]));
#pragma unroll
            for (int off = 1; off < 16; off <<= 1)
                mx = fmaxf(mx, __shfl_xor_sync(0xffffffffu, mx, off));
            mnew[i]  = fmaxf(m_i[i], mx);
            alpha[i] = __expf(m_i[i] - mnew[i]);
            float r = 0.f;
#pragma unroll
            for (int j = 0; j < 4; j++) {
                float p = __expf(S[i][j] - mnew[i]);
                S[i][j] = p;
                r += p;
            }
#pragma unroll
            for (int off = 1; off < 16; off <<= 1)
                r += __shfl_xor_sync(0xffffffffu, r, off);
            rs[i] = r;
        }
#pragma unroll
        for (int i = 0; i < 4; i++) {
            l_i[i] = l_i[i] * alpha[i] + rs[i];
            m_i[i] = mnew[i];
#pragma unroll
            for (int j = 0; j < 4; j++) O[i][j] *= alpha[i];
        }

        // stage P to smem: Ps[row][key]
#pragma unroll
        for (int i = 0; i < 4; i++)
            *reinterpret_cast<float4*>(&Ps[(ty * 4 + i) * FP + tx * 4]) =
                make_float4(S[i][0], S[i][1], S[i][2], S[i][3]);
        __syncthreads();

        // O += P . V
#pragma unroll 8
        for (int kk = 0; kk < 64; kk++) {
            const float4 v4 = *reinterpret_cast<const float4*>(&Vs[kk * FP + tx * 4]);
            const float p0 = Ps[(ty * 4 + 0) * FP + kk];
            const float p1 = Ps[(ty * 4 + 1) * FP + kk];
            const float p2 = Ps[(ty * 4 + 2) * FP + kk];
            const float p3 = Ps[(ty * 4 + 3) * FP + kk];
            O[0][0] += p0 * v4.x; O[0][1] += p0 * v4.y; O[0][2] += p0 * v4.z; O[0][3] += p0 * v4.w;
            O[1][0] += p1 * v4.x; O[1][1] += p1 * v4.y; O[1][2] += p1 * v4.z; O[1][3] += p1 * v4.w;
            O[2][0] += p2 * v4.x; O[2][1] += p2 * v4.y; O[2][2] += p2 * v4.z; O[2][3] += p2 * v4.w;
            O[3][0] += p3 * v4.x; O[3][1] += p3 * v4.y; O[3][2] += p3 * v4.z; O[3][3] += p3 * v4.w;
        }
    }

    // normalize + write y[b, t, h*64 + lat]
#pragma unroll
    for (int i = 0; i < 4; i++) {
        const float inv = 1.f / l_i[i];
        float4 o = make_float4(O[i][0] * inv, O[i][1] * inv,
                               O[i][2] * inv, O[i][3] * inv);
        *reinterpret_cast<float4*>(
            &Yg[base + (size_t)(qb * 64 + ty * 4 + i) * N_EMBD + tx * 4]) = o;
    }
}

// ---------------------------------------------------------------------------
// Host-side launcher (graph-capturable: kernel launches only)
// Input order per metadata: x, Wq, bq, Wk, bk, Wv, bv, Wo, bo, Wc
// ---------------------------------------------------------------------------
extern "C" void kernel_launch(void* const* d_in, const int* in_sizes, int n_in,
                              void* d_out, int out_size)
{
    const float* x  = (const float*)d_in[0];
    const float* Wq = (const float*)d_in[1];
    const float* bq = (const float*)d_in[2];
    const float* Wk = (const float*)d_in[3];
    const float* bk = (const float*)d_in[4];
    const float* Wv = (const float*)d_in[5];
    const float* bv = (const float*)d_in[6];
    const float* Wo = (const float*)d_in[7];
    const float* bo = (const float*)d_in[8];
    const float* Wc = (const float*)d_in[9];
    float* out = (float*)d_out;

    float *pWqc, *pbqc, *pqc, *pk, *pv, *py;
    cudaGetSymbolAddress((void**)&pWqc, g_Wqc);
    cudaGetSymbolAddress((void**)&pbqc, g_bqc);
    cudaGetSymbolAddress((void**)&pqc,  g_qc);
    cudaGetSymbolAddress((void**)&pk,   g_k);
    cudaGetSymbolAddress((void**)&pv,   g_v);
    cudaGetSymbolAddress((void**)&py,   g_y);

    cudaFuncSetAttribute(flash_attn,
                         cudaFuncAttributeMaxDynamicSharedMemorySize,
                         FLASH_SMEM);

    build_wqc<<<4096, 256>>>(Wq, Wc, bq, pWqc, pbqc);

    const dim3 gg(N_EMBD / 64, MROWS / 128);   // (16, 32)
    gemm_bias<<<gg, 256>>>(x, pWqc, pbqc, pqc, MROWS, N_EMBD, N_EMBD);
    gemm_bias<<<gg, 256>>>(x, Wk,   bk,   pk,  MROWS, N_EMBD, N_EMBD);
    gemm_bias<<<gg, 256>>>(x, Wv,   bv,   pv,  MROWS, N_EMBD, N_EMBD);

    flash_attn<<<dim3(SEQ / 64, BATCH * N_HEADS), 256, FLASH_SMEM>>>(pqc, pk, pv, py);

    gemm_bias<<<gg, 256>>>(py, Wo, bo, out, MROWS, N_EMBD, N_EMBD);
}

// round 4
// speedup vs baseline: 1.1693x; 1.1693x over previous
#include <cuda_runtime.h>
#include <cstddef>

// ---------------------------------------------------------------------------
// LatentAttention fp32 v2.1: B=2, T=2048, n_embd=1024, heads=16, latent=64
//   Wqc = per-head (Wq @ Wc)        (folds q-compression into q projection)
//   qc|k|v = x @ {Wqc,Wk,Wv} + b    (ONE fused launch, grid.z selects matrix)
//   y   = causal flash attention    (128q x 64k tiles, 8x4 micro, long-first)
//   out = y @ Wo + bo
// ---------------------------------------------------------------------------

#define N_EMBD   1024
#define N_HEADS  16
#define LATENT   64
#define BATCH    2
#define SEQ      2048
#define MROWS    (BATCH * SEQ)          // 4096
#define ATT_SCALE 0.125f                 // 1/sqrt(64)

// ------------------------- device scratch (no cudaMalloc allowed) ----------
__device__ float g_Wqc[N_EMBD * N_EMBD];
__device__ float g_bqc[N_EMBD];
__device__ float g_qkv[3 * MROWS * N_EMBD];   // [qc | k | v]
__device__ float g_y  [MROWS * N_EMBD];

// ---------------------------------------------------------------------------
// Wqc[c, h*64+l] = sum_d Wq[c, h*64+d] * Wc[d, l];   bqc likewise from bq.
// ---------------------------------------------------------------------------
__global__ void build_wqc(const float* __restrict__ Wq,
                          const float* __restrict__ Wc,
                          const float* __restrict__ bq,
                          float* __restrict__ Wqc,
                          float* __restrict__ bqc)
{
    int idx = blockIdx.x * blockDim.x + threadIdx.x;   // 0 .. 1024*1024-1
    int c   = idx >> 10;
    int col = idx & 1023;
    int h   = col >> 6;
    int l   = col & 63;
    const float* wrow = &Wq[(size_t)c * N_EMBD + h * LATENT];
    float s = 0.f;
#pragma unroll 8
    for (int d = 0; d < LATENT; d++)
        s += wrow[d] * Wc[d * LATENT + l];
    Wqc[idx] = s;
    if (c == 0) {
        float sb = 0.f;
#pragma unroll 8
        for (int d = 0; d < LATENT; d++)
            sb += bq[h * LATENT + d] * Wc[d * LATENT + l];
        bqc[col] = sb;
    }
}

// ---------------------------------------------------------------------------
// GEMM core: C[M,N] = A[M,K] @ W[K,N] + bias[N]
// 128x128 block tile, BK=8, 256 threads, 8x8 per-thread microtile,
// double-buffered smem, register-prefetched global loads.
// ---------------------------------------------------------------------------
__device__ __forceinline__
void gemm_body(const float* __restrict__ A,
               const float* __restrict__ W,
               const float* __restrict__ bias,
               float* __restrict__ C,
               int M, int N, int K, int bx, int by)
{
    __shared__ float As[2][8][132];   // As[buf][k][m]  (+4 pad)
    __shared__ float Bs[2][8][132];   // Bs[buf][k][n]

    const int tid = threadIdx.x;
    const int tx  = tid & 15;         // n group: cols tx*4 and 64+tx*4
    const int ty  = tid >> 4;         // m group: rows ty*4 and 64+ty*4
    const int m0  = by * 128;
    const int n0  = bx * 128;

    const int row_a = tid >> 1;               // 0..127
    const int kka   = (tid & 1) << 2;         // 0 or 4
    const int row_b = tid >> 5;               // 0..7
    const int colb  = (tid & 31) << 2;        // 0..124

    const float* Aptr = A + (size_t)(m0 + row_a) * K + kka;
    const float* Bptr = W + (size_t)row_b * N + n0 + colb;

    float acc[8][8];
#pragma unroll
    for (int i = 0; i < 8; i++)
#pragma unroll
        for (int j = 0; j < 8; j++) acc[i][j] = 0.f;

    // preload tile 0
    {
        const float4 a = *reinterpret_cast<const float4*>(Aptr);
        const float4 b = *reinterpret_cast<const float4*>(Bptr);
        As[0][kka + 0][row_a] = a.x;
        As[0][kka + 1][row_a] = a.y;
        As[0][kka + 2][row_a] = a.z;
        As[0][kka + 3][row_a] = a.w;
        *reinterpret_cast<float4*>(&Bs[0][row_b][colb]) = b;
    }
    __syncthreads();

    int buf = 0;
    for (int k0 = 8; k0 < K; k0 += 8) {
        const float4 an = *reinterpret_cast<const float4*>(Aptr + k0);
        const float4 bn = *reinterpret_cast<const float4*>(Bptr + (size_t)k0 * N);

#pragma unroll
        for (int kk = 0; kk < 8; kk++) {
            const float4 a0 = *reinterpret_cast<const float4*>(&As[buf][kk][ty * 4]);
            const float4 a1 = *reinterpret_cast<const float4*>(&As[buf][kk][64 + ty * 4]);
            const float4 b0 = *reinterpret_cast<const float4*>(&Bs[buf][kk][tx * 4]);
            const float4 b1 = *reinterpret_cast<const float4*>(&Bs[buf][kk][64 + tx * 4]);
            const float av[8] = {a0.x, a0.y, a0.z, a0.w, a1.x, a1.y, a1.z, a1.w};
            const float bv[8] = {b0.x, b0.y, b0.z, b0.w, b1.x, b1.y, b1.z, b1.w};
#pragma unroll
            for (int i = 0; i < 8; i++)
#pragma unroll
                for (int j = 0; j < 8; j++)
                    acc[i][j] += av[i] * bv[j];
        }

        const int nb = buf ^ 1;
        As[nb][kka + 0][row_a] = an.x;
        As[nb][kka + 1][row_a] = an.y;
        As[nb][kka + 2][row_a] = an.z;
        As[nb][kka + 3][row_a] = an.w;
        *reinterpret_cast<float4*>(&Bs[nb][row_b][colb]) = bn;
        __syncthreads();
        buf = nb;
    }

    // final tile
#pragma unroll
    for (int kk = 0; kk < 8; kk++) {
        const float4 a0 = *reinterpret_cast<const float4*>(&As[buf][kk][ty * 4]);
        const float4 a1 = *reinterpret_cast<const float4*>(&As[buf][kk][64 + ty * 4]);
        const float4 b0 = *reinterpret_cast<const float4*>(&Bs[buf][kk][tx * 4]);
        const float4 b1 = *reinterpret_cast<const float4*>(&Bs[buf][kk][64 + tx * 4]);
        const float av[8] = {a0.x, a0.y, a0.z, a0.w, a1.x, a1.y, a1.z, a1.w};
        const float bv[8] = {b0.x, b0.y, b0.z, b0.w, b1.x, b1.y, b1.z, b1.w};
#pragma unroll
        for (int i = 0; i < 8; i++)
#pragma unroll
            for (int j = 0; j < 8; j++)
                acc[i][j] += av[i] * bv[j];
    }

    // epilogue: bias + writeback
    const float4 bb0 = *reinterpret_cast<const float4*>(&bias[n0 + tx * 4]);
    const float4 bb1 = *reinterpret_cast<const float4*>(&bias[n0 + 64 + tx * 4]);
    const float bl[8] = {bb0.x, bb0.y, bb0.z, bb0.w, bb1.x, bb1.y, bb1.z, bb1.w};
#pragma unroll
    for (int i = 0; i < 8; i++) {
        const int row = m0 + ((i < 4) ? (ty * 4 + i) : (64 + ty * 4 + i - 4));
        float4 o0 = make_float4(acc[i][0] + bl[0], acc[i][1] + bl[1],
                                acc[i][2] + bl[2], acc[i][3] + bl[3]);
        float4 o1 = make_float4(acc[i][4] + bl[4], acc[i][5] + bl[5],
                                acc[i][6] + bl[6], acc[i][7] + bl[7]);
        *reinterpret_cast<float4*>(&C[(size_t)row * N + n0 + tx * 4])      = o0;
        *reinterpret_cast<float4*>(&C[(size_t)row * N + n0 + 64 + tx * 4]) = o1;
    }
}

// single GEMM (output projection)
__global__ __launch_bounds__(256, 2)
void gemm_bias(const float* __restrict__ A,
               const float* __restrict__ W,
               const float* __restrict__ bias,
               float* __restrict__ C,
               int M, int N, int K)
{
    gemm_body(A, W, bias, C, M, N, K, blockIdx.x, blockIdx.y);
}

// fused QKV projection: grid.z in {0,1,2} selects {Wqc,Wk,Wv}
__global__ __launch_bounds__(256, 2)
void gemm_qkv(const float* __restrict__ x,
              const float* __restrict__ Wqc, const float* __restrict__ bqc,
              const float* __restrict__ Wk,  const float* __restrict__ bk,
              const float* __restrict__ Wv,  const float* __restrict__ bv,
              float* __restrict__ Cqkv)
{
    const int z = blockIdx.z;
    const float* W = (z == 0) ? Wqc : (z == 1) ? Wk : Wv;
    const float* b = (z == 0) ? bqc : (z == 1) ? bk : bv;
    float* C = Cqkv + (size_t)z * MROWS * N_EMBD;
    gemm_body(x, W, b, C, MROWS, N_EMBD, N_EMBD, blockIdx.x, blockIdx.y);
}

// ---------------------------------------------------------------------------
// Flash attention v2: 128 query rows x 64 keys per iteration.
// 256 threads, 8x4 microtile for S, P staged row-major, PV float4 on P.
// Long blocks (high qb) launch first for better last-wave packing.
// smem = 103424 B -> 2 blocks/SM.
// ---------------------------------------------------------------------------
#define RQ 132
#define RK 68
#define RV 68
#define RP 68
#define FLASH_SMEM ((64 * RQ + 64 * RK + 64 * RV + 128 * RP) * (int)sizeof(float))

__global__ __launch_bounds__(256)
void flash_attn(const float* __restrict__ Qg,
                const float* __restrict__ Kg,
                const float* __restrict__ Vg,
                float* __restrict__ Yg)
{
    extern __shared__ float sm[];
    float* Qs = sm;                      // [64 lat][RQ]   (lat-major, 128 rows)
    float* Ks = Qs + 64 * RQ;            // [64 lat][RK]   (lat-major, 64 keys)
    float* Vs = Ks + 64 * RK;            // [64 key][RV]
    float* Ps = Vs + 64 * RV;            // [128 row][RP]

    const int tid = threadIdx.x;
    const int tx  = tid & 15;            // key / latent group (4 wide)
    const int ty  = tid >> 4;            // query row group
    const int qb  = gridDim.x - 1 - blockIdx.x;   // longest work first
    const int bh  = blockIdx.y;          // 0..31
    const int b   = bh >> 4;
    const int h   = bh & 15;
    const size_t base = (size_t)b * SEQ * N_EMBD + (size_t)h * LATENT;

    int rloc[8];
#pragma unroll
    for (int i = 0; i < 8; i++)
        rloc[i] = (i < 4) ? (ty * 4 + i) : (64 + ty * 4 + i - 4);

    // load Q tile (128 rows x 64 lat) transposed -> Qs[lat][row]
#pragma unroll
    for (int i = 0; i < 8; i++) {
        int q   = tid + i * 256;          // 0..2047
        int row = q >> 4;                 // 0..127
        int lat = (q & 15) << 2;
        const float4 v4 = *reinterpret_cast<const float4*>(
            &Qg[base + (size_t)(qb * 128 + row) * N_EMBD + lat]);
        Qs[(lat + 0) * RQ + row] = v4.x;
        Qs[(lat + 1) * RQ + row] = v4.y;
        Qs[(lat + 2) * RQ + row] = v4.z;
        Qs[(lat + 3) * RQ + row] = v4.w;
    }

    float m_i[8], l_i[8], O[8][4];
#pragma unroll
    for (int i = 0; i < 8; i++) {
        m_i[i] = -1e30f;
        l_i[i] = 0.f;
#pragma unroll
        for (int j = 0; j < 4; j++) O[i][j] = 0.f;
    }

    const int jmax = 2 * qb + 1;          // last key tile (inclusive)
    for (int jb = 0; jb <= jmax; jb++) {
        __syncthreads();
        // load K (transposed) + V (natural) tiles of 64 keys
#pragma unroll
        for (int i = 0; i < 4; i++) {
            int q   = tid + i * 256;
            int key = q >> 4;             // 0..63
            int lat = (q & 15) << 2;
            const size_t goff = base + (size_t)(jb * 64 + key) * N_EMBD + lat;
            const float4 kv = *reinterpret_cast<const float4*>(&Kg[goff]);
            Ks[(lat + 0) * RK + key] = kv.x;
            Ks[(lat + 1) * RK + key] = kv.y;
            Ks[(lat + 2) * RK + key] = kv.z;
            Ks[(lat + 3) * RK + key] = kv.w;
            const float4 vv = *reinterpret_cast<const float4*>(&Vg[goff]);
            *reinterpret_cast<float4*>(&Vs[key * RV + lat]) = vv;
        }
        __syncthreads();

        // S = (Q . K^T) * scale, 8x4 per thread
        float S[8][4];
#pragma unroll
        for (int i = 0; i < 8; i++)
#pragma unroll
            for (int j = 0; j < 4; j++) S[i][j] = 0.f;

#pragma unroll 8
        for (int kk = 0; kk < 64; kk++) {
            const float4 q0 = *reinterpret_cast<const float4*>(&Qs[kk * RQ + ty * 4]);
            const float4 q1 = *reinterpret_cast<const float4*>(&Qs[kk * RQ + 64 + ty * 4]);
            const float4 kv = *reinterpret_cast<const float4*>(&Ks[kk * RK + tx * 4]);
            const float qv[8] = {q0.x, q0.y, q0.z, q0.w, q1.x, q1.y, q1.z, q1.w};
            const float kl[4] = {kv.x, kv.y, kv.z, kv.w};
#pragma unroll
            for (int i = 0; i < 8; i++)
#pragma unroll
                for (int j = 0; j < 4; j++)
                    S[i][j] += qv[i] * kl[j];
        }
#pragma unroll
        for (int i = 0; i < 8; i++)
#pragma unroll
            for (int j = 0; j < 4; j++) S[i][j] *= ATT_SCALE;

        if (jb >= 2 * qb) {               // diagonal region: causal mask
#pragma unroll
            for (int i = 0; i < 8; i++) {
                const int rg = qb * 128 + rloc[i];
#pragma unroll
                for (int j = 0; j < 4; j++)
                    if (jb * 64 + tx * 4 + j > rg) S[i][j] = -1e30f;
            }
        }

        // online softmax: row reductions across the 16 tx lanes
#pragma unroll
        for (int i = 0; i < 8; i++) {
            float mx = fmaxf(fmaxf(S[i][0], S[i][1]), fmaxf(S[i][2], S[i][3]));
#pragma unroll
            for (int off = 1; off < 16; off <<= 1)
                mx = fmaxf(mx, __shfl_xor_sync(0xffffffffu, mx, off));
            const float mnew  = fmaxf(m_i[i], mx);
            const float alpha = __expf(m_i[i] - mnew);
            float r = 0.f;
#pragma unroll
            for (int j = 0; j < 4; j++) {
                const float p = __expf(S[i][j] - mnew);
                S[i][j] = p;
                r += p;
            }
#pragma unroll
            for (int off = 1; off < 16; off <<= 1)
                r += __shfl_xor_sync(0xffffffffu, r, off);
            l_i[i] = l_i[i] * alpha + r;
            m_i[i] = mnew;
#pragma unroll
            for (int j = 0; j < 4; j++) O[i][j] *= alpha;
        }

        // stage P row-major (conflict-free float4)
#pragma unroll
        for (int i = 0; i < 8; i++)
            *reinterpret_cast<float4*>(&Ps[rloc[i] * RP + tx * 4]) =
                make_float4(S[i][0], S[i][1], S[i][2], S[i][3]);
        __syncthreads();

        // O += P . V   (kk unrolled x4 so P rows load as float4)
#pragma unroll 4
        for (int t = 0; t < 16; t++) {
            const float4 v0 = *reinterpret_cast<const float4*>(&Vs[(4 * t + 0) * RV + tx * 4]);
            const float4 v1 = *reinterpret_cast<const float4*>(&Vs[(4 * t + 1) * RV + tx * 4]);
            const float4 v2 = *reinterpret_cast<const float4*>(&Vs[(4 * t + 2) * RV + tx * 4]);
            const float4 v3 = *reinterpret_cast<const float4*>(&Vs[(4 * t + 3) * RV + tx * 4]);
#pragma unroll
            for (int i = 0; i < 8; i++) {
                const float4 p = *reinterpret_cast<const float4*>(&Ps[rloc[i] * RP + 4 * t]);
                O[i][0] += p.x * v0.x + p.y * v1.x + p.z * v2.x + p.w * v3.x;
                O[i][1] += p.x * v0.y + p.y * v1.y + p.z * v2.y + p.w * v3.y;
                O[i][2] += p.x * v0.z + p.y * v1.z + p.z * v2.z + p.w * v3.z;
                O[i][3] += p.x * v0.w + p.y * v1.w + p.z * v2.w + p.w * v3.w;
            }
        }
    }

    // normalize + write y
#pragma unroll
    for (int i = 0; i < 8; i++) {
        const float inv = 1.f / l_i[i];
        float4 o = make_float4(O[i][0] * inv, O[i][1] * inv,
                               O[i][2] * inv, O[i][3] * inv);
        *reinterpret_cast<float4*>(
            &Yg[base + (size_t)(qb * 128 + rloc[i]) * N_EMBD + tx * 4]) = o;
    }
}

// ---------------------------------------------------------------------------
// Launcher (graph-capturable). Inputs: x,Wq,bq,Wk,bk,Wv,bv,Wo,bo,Wc
// ---------------------------------------------------------------------------
extern "C" void kernel_launch(void* const* d_in, const int* in_sizes, int n_in,
                              void* d_out, int out_size)
{
    const float* x  = (const float*)d_in[0];
    const float* Wq = (const float*)d_in[1];
    const float* bq = (const float*)d_in[2];
    const float* Wk = (const float*)d_in[3];
    const float* bk = (const float*)d_in[4];
    const float* Wv = (const float*)d_in[5];
    const float* bv = (const float*)d_in[6];
    const float* Wo = (const float*)d_in[7];
    const float* bo = (const float*)d_in[8];
    const float* Wc = (const float*)d_in[9];
    float* out = (float*)d_out;

    float *pWqc, *pbqc, *pqkv, *py;
    cudaGetSymbolAddress((void**)&pWqc, g_Wqc);
    cudaGetSymbolAddress((void**)&pbqc, g_bqc);
    cudaGetSymbolAddress((void**)&pqkv, g_qkv);
    cudaGetSymbolAddress((void**)&py,   g_y);

    float* pqc = pqkv;
    float* pk  = pqkv + (size_t)MROWS * N_EMBD;
    float* pv  = pqkv + (size_t)2 * MROWS * N_EMBD;

    cudaFuncSetAttribute(flash_attn,
                         cudaFuncAttributeMaxDynamicSharedMemorySize,
                         FLASH_SMEM);

    build_wqc<<<4096, 256>>>(Wq, Wc, bq, pWqc, pbqc);

    const dim3 gq(N_EMBD / 128, MROWS / 128, 3);   // (8, 32, 3) fused QKV
    gemm_qkv<<<gq, 256>>>(x, pWqc, pbqc, Wk, bk, Wv, bv, pqkv);

    flash_attn<<<dim3(SEQ / 128, BATCH * N_HEADS), 256, FLASH_SMEM>>>(pqc, pk, pv, py);

    const dim3 gg(N_EMBD / 128, MROWS / 128);      // (8, 32)
    gemm_bias<<<gg, 256>>>(py, Wo, bo, out, MROWS, N_EMBD, N_EMBD);
}

// round 6
// speedup vs baseline: 1.4821x; 1.2676x over previous
#include <cuda_runtime.h>
#include <cuda_bf16.h>
#include <cstdint>
#include <cstddef>

// ---------------------------------------------------------------------------
// LatentAttention v3: B=2, T=2048, n_embd=1024, heads=16, latent=64
//   - 4 big GEMMs on tensor cores: bf16x3 error-compensated split
//     (a = a_hi + a_lo, bf16;  a*b = hi*hi + hi*lo + lo*hi, fp32 accum)
//   - flash attention stays fp32 (unchanged from v2.1)
// (Byte-identical resubmission: prior round was an infra failure.)
// ---------------------------------------------------------------------------

#define N_EMBD   1024
#define N_HEADS  16
#define LATENT   64
#define BATCH    2
#define SEQ      2048
#define MROWS    (BATCH * SEQ)          // 4096
#define KDIM     1024
#define ATT_SCALE 0.125f

typedef __nv_bfloat16  bf16;
typedef __nv_bfloat162 bf162;

// ------------------------- device scratch ----------------------------------
__device__ float g_Wqc[N_EMBD * N_EMBD];
__device__ float g_bqc[N_EMBD];
__device__ float g_qkv[3 * MROWS * N_EMBD];     // [qc | k | v] fp32
__device__ float g_y  [MROWS * N_EMBD];         // attention output fp32

__device__ bf16  g_xs_hi[MROWS * N_EMBD];       // split of x
__device__ bf16  g_xs_lo[MROWS * N_EMBD];
__device__ bf16  g_ys_hi[MROWS * N_EMBD];       // split of y
__device__ bf16  g_ys_lo[MROWS * N_EMBD];
// transposed split weights, [N][K] layout: 0=Wqc 1=Wk 2=Wv 3=Wo
__device__ bf16  g_wt_hi[4][N_EMBD * N_EMBD];
__device__ bf16  g_wt_lo[4][N_EMBD * N_EMBD];

// ---------------------------------------------------------------------------
// Wqc[c, h*64+l] = sum_d Wq[c, h*64+d] * Wc[d, l];  bqc likewise from bq.
// ---------------------------------------------------------------------------
__global__ void build_wqc(const float* __restrict__ Wq,
                          const float* __restrict__ Wc,
                          const float* __restrict__ bq,
                          float* __restrict__ Wqc,
                          float* __restrict__ bqc)
{
    int idx = blockIdx.x * blockDim.x + threadIdx.x;
    int c   = idx >> 10;
    int col = idx & 1023;
    int h   = col >> 6;
    int l   = col & 63;
    const float* wrow = &Wq[(size_t)c * N_EMBD + h * LATENT];
    float s = 0.f;
#pragma unroll 8
    for (int d = 0; d < LATENT; d++)
        s += wrow[d] * Wc[d * LATENT + l];
    Wqc[idx] = s;
    if (c == 0) {
        float sb = 0.f;
#pragma unroll 8
        for (int d = 0; d < LATENT; d++)
            sb += bq[h * LATENT + d] * Wc[d * LATENT + l];
        bqc[col] = sb;
    }
}

// ---------------------------------------------------------------------------
// Elementwise split: fp32 -> bf16 hi + bf16 lo (2 elems / thread)
// ---------------------------------------------------------------------------
__global__ void split2(const float* __restrict__ src,
                       bf162* __restrict__ hi, bf162* __restrict__ lo, int n2)
{
    int i = blockIdx.x * blockDim.x + threadIdx.x;
    if (i >= n2) return;
    const float2 v = reinterpret_cast<const float2*>(src)[i];
    bf16 h0 = __float2bfloat16(v.x);
    bf16 h1 = __float2bfloat16(v.y);
    bf16 l0 = __float2bfloat16(v.x - __bfloat162float(h0));
    bf16 l1 = __float2bfloat16(v.y - __bfloat162float(h1));
    hi[i] = bf162(h0, h1);
    lo[i] = bf162(l0, l1);
}

// ---------------------------------------------------------------------------
// Transpose + split: W[K][N] fp32 -> Th[N][K], Tl[N][K] bf16
// block (32,8), 32x32 tile via smem
// ---------------------------------------------------------------------------
__global__ void tsplit(const float* __restrict__ W,
                       bf16* __restrict__ Th, bf16* __restrict__ Tl)
{
    __shared__ float t[32][33];
    const int tx = threadIdx.x, ty = threadIdx.y;
    const int n0 = blockIdx.x * 32, k0 = blockIdx.y * 32;
#pragma unroll
    for (int i = 0; i < 4; i++)
        t[ty + 8 * i][tx] = W[(size_t)(k0 + ty + 8 * i) * N_EMBD + n0 + tx];
    __syncthreads();
#pragma unroll
    for (int i = 0; i < 4; i++) {
        const int n = n0 + ty + 8 * i;
        const int k = k0 + tx;
        const float v = t[tx][ty + 8 * i];
        bf16 h = __float2bfloat16(v);
        bf16 l = __float2bfloat16(v - __bfloat162float(h));
        Th[(size_t)n * KDIM + k] = h;
        Tl[(size_t)n * KDIM + k] = l;
    }
}

// ---------------------------------------------------------------------------
// bf16x3 tensor-core GEMM body: C[M,N] = Ah+Al (M,K) @ (Bh+Bl)^T(N,K) + bias
// 128x128 tile, BK=32, 256 threads (8 warps as 2m x 4n, 64x32 per warp).
// smem rows padded to 20 words (40 bf16) -> conflict-free frag loads.
// ---------------------------------------------------------------------------
#define SMW 20   // smem row stride in 32-bit words

__device__ __forceinline__
void mma_bf16(float& d0, float& d1, float& d2, float& d3,
              uint32_t a0, uint32_t a1, uint32_t a2, uint32_t a3,
              uint32_t b0, uint32_t b1)
{
    asm volatile(
        "mma.sync.aligned.m16n8k16.row.col.f32.bf16.bf16.f32 "
        "{%0,%1,%2,%3}, {%4,%5,%6,%7}, {%8,%9}, {%0,%1,%2,%3};\n"
        : "+f"(d0), "+f"(d1), "+f"(d2), "+f"(d3)
        : "r"(a0), "r"(a1), "r"(a2), "r"(a3), "r"(b0), "r"(b1));
}

__device__ __forceinline__
void gemm3_body(const bf16* __restrict__ Ah, const bf16* __restrict__ Al,
                const bf16* __restrict__ Bh, const bf16* __restrict__ Bl,
                const float* __restrict__ bias, float* __restrict__ C,
                int M, int N, int K, int bx, int by)
{
    __shared__ __align__(16) uint32_t sAh[128][SMW];
    __shared__ __align__(16) uint32_t sAl[128][SMW];
    __shared__ __align__(16) uint32_t sBh[128][SMW];
    __shared__ __align__(16) uint32_t sBl[128][SMW];

    const int tid    = threadIdx.x;
    const int lane   = tid & 31;
    const int wid    = tid >> 5;
    const int warp_m = wid >> 2;            // 0..1
    const int warp_n = wid & 3;             // 0..3
    const int m0     = by * 128;
    const int n0     = bx * 128;
    const int lg     = lane >> 2;           // 0..7
    const int lc     = lane & 3;            // 0..3

    float acc[4][4][4];                      // [mfrag][nfrag][c0..c3]
#pragma unroll
    for (int i = 0; i < 4; i++)
#pragma unroll
        for (int j = 0; j < 4; j++)
#pragma unroll
            for (int c = 0; c < 4; c++) acc[i][j][c] = 0.f;

    for (int k0 = 0; k0 < K; k0 += 32) {
        __syncthreads();
#pragma unroll
        for (int it = 0; it < 2; it++) {
            const int idx = tid + it * 256;  // 0..511
            const int row = idx >> 2;        // 0..127
            const int q   = idx & 3;         // float4 slot (8 k each)
            const size_t ga = (size_t)(m0 + row) * K + k0 + q * 8;
            const size_t gb = (size_t)(n0 + row) * K + k0 + q * 8;
            const float4 vah = *reinterpret_cast<const float4*>(Ah + ga);
            const float4 val = *reinterpret_cast<const float4*>(Al + ga);
            const float4 vbh = *reinterpret_cast<const float4*>(Bh + gb);
            const float4 vbl = *reinterpret_cast<const float4*>(Bl + gb);
            *reinterpret_cast<float4*>(&sAh[row][q * 4]) = vah;
            *reinterpret_cast<float4*>(&sAl[row][q * 4]) = val;
            *reinterpret_cast<float4*>(&sBh[row][q * 4]) = vbh;
            *reinterpret_cast<float4*>(&sBl[row][q * 4]) = vbl;
        }
        __syncthreads();

#pragma unroll
        for (int ks = 0; ks < 2; ks++) {     // two k16 steps per BK=32
            const int kw = ks * 8;           // word base

            // B fragments for this warp's 4 n-tiles (hi & lo)
            uint32_t bh[4][2], bl[4][2];
#pragma unroll
            for (int j = 0; j < 4; j++) {
                const int n = warp_n * 32 + j * 8 + lg;
                bh[j][0] = sBh[n][kw + lc];
                bh[j][1] = sBh[n][kw + 4 + lc];
                bl[j][0] = sBl[n][kw + lc];
                bl[j][1] = sBl[n][kw + 4 + lc];
            }

#pragma unroll
            for (int i = 0; i < 4; i++) {
                const int r = warp_m * 64 + i * 16 + lg;
                uint32_t ah0 = sAh[r][kw + lc];
                uint32_t ah1 = sAh[r + 8][kw + lc];
                uint32_t ah2 = sAh[r][kw + 4 + lc];
                uint32_t ah3 = sAh[r + 8][kw + 4 + lc];
                uint32_t al0 = sAl[r][kw + lc];
                uint32_t al1 = sAl[r + 8][kw + lc];
                uint32_t al2 = sAl[r][kw + 4 + lc];
                uint32_t al3 = sAl[r + 8][kw + 4 + lc];
#pragma unroll
                for (int j = 0; j < 4; j++) {
                    float* d = acc[i][j];
                    mma_bf16(d[0], d[1], d[2], d[3], ah0, ah1, ah2, ah3,
                             bh[j][0], bh[j][1]);
                    mma_bf16(d[0], d[1], d[2], d[3], ah0, ah1, ah2, ah3,
                             bl[j][0], bl[j][1]);
                    mma_bf16(d[0], d[1], d[2], d[3], al0, al1, al2, al3,
                             bh[j][0], bh[j][1]);
                }
            }
        }
    }

    // epilogue: bias + writeback
#pragma unroll
    for (int j = 0; j < 4; j++) {
        const int cn = n0 + warp_n * 32 + j * 8 + 2 * lc;
        const float2 bb = *reinterpret_cast<const float2*>(&bias[cn]);
#pragma unroll
        for (int i = 0; i < 4; i++) {
            const int r0 = m0 + warp_m * 64 + i * 16 + lg;
            float2 o0 = make_float2(acc[i][j][0] + bb.x, acc[i][j][1] + bb.y);
            float2 o1 = make_float2(acc[i][j][2] + bb.x, acc[i][j][3] + bb.y);
            *reinterpret_cast<float2*>(&C[(size_t)r0 * N + cn])       = o0;
            *reinterpret_cast<float2*>(&C[(size_t)(r0 + 8) * N + cn]) = o1;
        }
    }
}

// fused QKV projection: grid.z selects {Wqc,Wk,Wv}
__global__ __launch_bounds__(256)
void gemm_qkv_mma(const bf16* __restrict__ xh, const bf16* __restrict__ xl,
                  const float* __restrict__ bqc,
                  const float* __restrict__ bk,
                  const float* __restrict__ bv,
                  float* __restrict__ Cqkv)
{
    const int z = blockIdx.z;
    const bf16* Bh = g_wt_hi[z];
    const bf16* Bl = g_wt_lo[z];
    const float* b = (z == 0) ? bqc : (z == 1) ? bk : bv;
    float* C = Cqkv + (size_t)z * MROWS * N_EMBD;
    gemm3_body(xh, xl, Bh, Bl, b, C, MROWS, N_EMBD, KDIM,
               blockIdx.x, blockIdx.y);
}

// output projection: y @ Wo + bo
__global__ __launch_bounds__(256)
void gemm_out_mma(const bf16* __restrict__ yh, const bf16* __restrict__ yl,
                  const float* __restrict__ bo, float* __restrict__ C)
{
    gemm3_body(yh, yl, g_wt_hi[3], g_wt_lo[3], bo, C, MROWS, N_EMBD, KDIM,
               blockIdx.x, blockIdx.y);
}

// ---------------------------------------------------------------------------
// Flash attention (fp32, unchanged from v2.1): 128q x 64k tiles, 8x4 micro.
// ---------------------------------------------------------------------------
#define RQ 132
#define RK 68
#define RV 68
#define RP 68
#define FLASH_SMEM ((64 * RQ + 64 * RK + 64 * RV + 128 * RP) * (int)sizeof(float))

__global__ __launch_bounds__(256)
void flash_attn(const float* __restrict__ Qg,
                const float* __restrict__ Kg,
                const float* __restrict__ Vg,
                float* __restrict__ Yg)
{
    extern __shared__ float sm[];
    float* Qs = sm;
    float* Ks = Qs + 64 * RQ;
    float* Vs = Ks + 64 * RK;
    float* Ps = Vs + 64 * RV;

    const int tid = threadIdx.x;
    const int tx  = tid & 15;
    const int ty  = tid >> 4;
    const int qb  = gridDim.x - 1 - blockIdx.x;   // longest work first
    const int bh  = blockIdx.y;
    const int b   = bh >> 4;
    const int h   = bh & 15;
    const size_t base = (size_t)b * SEQ * N_EMBD + (size_t)h * LATENT;

    int rloc[8];
#pragma unroll
    for (int i = 0; i < 8; i++)
        rloc[i] = (i < 4) ? (ty * 4 + i) : (64 + ty * 4 + i - 4);

#pragma unroll
    for (int i = 0; i < 8; i++) {
        int q   = tid + i * 256;
        int row = q >> 4;
        int lat = (q & 15) << 2;
        const float4 v4 = *reinterpret_cast<const float4*>(
            &Qg[base + (size_t)(qb * 128 + row) * N_EMBD + lat]);
        Qs[(lat + 0) * RQ + row] = v4.x;
        Qs[(lat + 1) * RQ + row] = v4.y;
        Qs[(lat + 2) * RQ + row] = v4.z;
        Qs[(lat + 3) * RQ + row] = v4.w;
    }

    float m_i[8], l_i[8], O[8][4];
#pragma unroll
    for (int i = 0; i < 8; i++) {
        m_i[i] = -1e30f;
        l_i[i] = 0.f;
#pragma unroll
        for (int j = 0; j < 4; j++) O[i][j] = 0.f;
    }

    const int jmax = 2 * qb + 1;
    for (int jb = 0; jb <= jmax; jb++) {
        __syncthreads();
#pragma unroll
        for (int i = 0; i < 4; i++) {
            int q   = tid + i * 256;
            int key = q >> 4;
            int lat = (q & 15) << 2;
            const size_t goff = base + (size_t)(jb * 64 + key) * N_EMBD + lat;
            const float4 kv = *reinterpret_cast<const float4*>(&Kg[goff]);
            Ks[(lat + 0) * RK + key] = kv.x;
            Ks[(lat + 1) * RK + key] = kv.y;
            Ks[(lat + 2) * RK + key] = kv.z;
            Ks[(lat + 3) * RK + key] = kv.w;
            const float4 vv = *reinterpret_cast<const float4*>(&Vg[goff]);
            *reinterpret_cast<float4*>(&Vs[key * RV + lat]) = vv;
        }
        __syncthreads();

        float S[8][4];
#pragma unroll
        for (int i = 0; i < 8; i++)
#pragma unroll
            for (int j = 0; j < 4; j++) S[i][j] = 0.f;

#pragma unroll 8
        for (int kk = 0; kk < 64; kk++) {
            const float4 q0 = *reinterpret_cast<const float4*>(&Qs[kk * RQ + ty * 4]);
            const float4 q1 = *reinterpret_cast<const float4*>(&Qs[kk * RQ + 64 + ty * 4]);
            const float4 kv = *reinterpret_cast<const float4*>(&Ks[kk * RK + tx * 4]);
            const float qv[8] = {q0.x, q0.y, q0.z, q0.w, q1.x, q1.y, q1.z, q1.w};
            const float kl[4] = {kv.x, kv.y, kv.z, kv.w};
#pragma unroll
            for (int i = 0; i < 8; i++)
#pragma unroll
                for (int j = 0; j < 4; j++)
                    S[i][j] += qv[i] * kl[j];
        }
#pragma unroll
        for (int i = 0; i < 8; i++)
#pragma unroll
            for (int j = 0; j < 4; j++) S[i][j] *= ATT_SCALE;

        if (jb >= 2 * qb) {
#pragma unroll
            for (int i = 0; i < 8; i++) {
                const int rg = qb * 128 + rloc[i];
#pragma unroll
                for (int j = 0; j < 4; j++)
                    if (jb * 64 + tx * 4 + j > rg) S[i][j] = -1e30f;
            }
        }

#pragma unroll
        for (int i = 0; i < 8; i++) {
            float mx = fmaxf(fmaxf(S[i][0], S[i][1]), fmaxf(S[i][2], S[i][3]));
#pragma unroll
            for (int off = 1; off < 16; off <<= 1)
                mx = fmaxf(mx, __shfl_xor_sync(0xffffffffu, mx, off));
            const float mnew  = fmaxf(m_i[i], mx);
            const float alpha = __expf(m_i[i] - mnew);
            float r = 0.f;
#pragma unroll
            for (int j = 0; j < 4; j++) {
                const float p = __expf(S[i][j] - mnew);
                S[i][j] = p;
                r += p;
            }
#pragma unroll
            for (int off = 1; off < 16; off <<= 1)
                r += __shfl_xor_sync(0xffffffffu, r, off);
            l_i[i] = l_i[i] * alpha + r;
            m_i[i] = mnew;
#pragma unroll
            for (int j = 0; j < 4; j++) O[i][j] *= alpha;
        }

#pragma unroll
        for (int i = 0; i < 8; i++)
            *reinterpret_cast<float4*>(&Ps[rloc[i] * RP + tx * 4]) =
                make_float4(S[i][0], S[i][1], S[i][2], S[i][3]);
        __syncthreads();

#pragma unroll 4
        for (int t = 0; t < 16; t++) {
            const float4 v0 = *reinterpret_cast<const float4*>(&Vs[(4 * t + 0) * RV + tx * 4]);
            const float4 v1 = *reinterpret_cast<const float4*>(&Vs[(4 * t + 1) * RV + tx * 4]);
            const float4 v2 = *reinterpret_cast<const float4*>(&Vs[(4 * t + 2) * RV + tx * 4]);
            const float4 v3 = *reinterpret_cast<const float4*>(&Vs[(4 * t + 3) * RV + tx * 4]);
#pragma unroll
            for (int i = 0; i < 8; i++) {
                const float4 p = *reinterpret_cast<const float4*>(&Ps[rloc[i] * RP + 4 * t]);
                O[i][0] += p.x * v0.x + p.y * v1.x + p.z * v2.x + p.w * v3.x;
                O[i][1] += p.x * v0.y + p.y * v1.y + p.z * v2.y + p.w * v3.y;
                O[i][2] += p.x * v0.z + p.y * v1.z + p.z * v2.z + p.w * v3.z;
                O[i][3] += p.x * v0.w + p.y * v1.w + p.z * v2.w + p.w * v3.w;
            }
        }
    }

#pragma unroll
    for (int i = 0; i < 8; i++) {
        const float inv = 1.f / l_i[i];
        float4 o = make_float4(O[i][0] * inv, O[i][1] * inv,
                               O[i][2] * inv, O[i][3] * inv);
        *reinterpret_cast<float4*>(
            &Yg[base + (size_t)(qb * 128 + rloc[i]) * N_EMBD + tx * 4]) = o;
    }
}

// ---------------------------------------------------------------------------
// Launcher. Inputs: x,Wq,bq,Wk,bk,Wv,bv,Wo,bo,Wc
// ---------------------------------------------------------------------------
extern "C" void kernel_launch(void* const* d_in, const int* in_sizes, int n_in,
                              void* d_out, int out_size)
{
    const float* x  = (const float*)d_in[0];
    const float* Wq = (const float*)d_in[1];
    const float* bq = (const float*)d_in[2];
    const float* Wk = (const float*)d_in[3];
    const float* bk = (const float*)d_in[4];
    const float* Wv = (const float*)d_in[5];
    const float* bv = (const float*)d_in[6];
    const float* Wo = (const float*)d_in[7];
    const float* bo = (const float*)d_in[8];
    const float* Wc = (const float*)d_in[9];
    float* out = (float*)d_out;

    float *pWqc, *pbqc, *pqkv, *py;
    bf16 *pxh, *pxl, *pyh, *pyl, *pwh, *pwl;
    cudaGetSymbolAddress((void**)&pWqc, g_Wqc);
    cudaGetSymbolAddress((void**)&pbqc, g_bqc);
    cudaGetSymbolAddress((void**)&pqkv, g_qkv);
    cudaGetSymbolAddress((void**)&py,   g_y);
    cudaGetSymbolAddress((void**)&pxh,  g_xs_hi);
    cudaGetSymbolAddress((void**)&pxl,  g_xs_lo);
    cudaGetSymbolAddress((void**)&pyh,  g_ys_hi);
    cudaGetSymbolAddress((void**)&pyl,  g_ys_lo);
    cudaGetSymbolAddress((void**)&pwh,  g_wt_hi);
    cudaGetSymbolAddress((void**)&pwl,  g_wt_lo);

    float* pqc = pqkv;
    float* pk  = pqkv + (size_t)MROWS * N_EMBD;
    float* pv  = pqkv + (size_t)2 * MROWS * N_EMBD;

    cudaFuncSetAttribute(flash_attn,
                         cudaFuncAttributeMaxDynamicSharedMemorySize,
                         FLASH_SMEM);

    // --- prep: Wqc build, splits, weight transpose-splits -------------------
    build_wqc<<<4096, 256>>>(Wq, Wc, bq, pWqc, pbqc);

    const int n2x = MROWS * N_EMBD / 2;
    split2<<<(n2x + 255) / 256, 256>>>(x, (bf162*)pxh, (bf162*)pxl, n2x);

    const dim3 tg(N_EMBD / 32, N_EMBD / 32);
    const dim3 tb(32, 8);
    const size_t WSZ = (size_t)N_EMBD * N_EMBD;
    tsplit<<<tg, tb>>>(pWqc, pwh + 0 * WSZ, pwl + 0 * WSZ);
    tsplit<<<tg, tb>>>(Wk,   pwh + 1 * WSZ, pwl + 1 * WSZ);
    tsplit<<<tg, tb>>>(Wv,   pwh + 2 * WSZ, pwl + 2 * WSZ);
    tsplit<<<tg, tb>>>(Wo,   pwh + 3 * WSZ, pwl + 3 * WSZ);

    // --- QKV projection (tensor cores) --------------------------------------
    const dim3 gq(N_EMBD / 128, MROWS / 128, 3);
    gemm_qkv_mma<<<gq, 256>>>(pxh, pxl, pbqc, bk, bv, pqkv);

    // --- attention (fp32) ----------------------------------------------------
    flash_attn<<<dim3(SEQ / 128, BATCH * N_HEADS), 256, FLASH_SMEM>>>(pqc, pk, pv, py);

    // --- output projection (tensor cores) ------------------------------------
    split2<<<(n2x + 255) / 256, 256>>>(py, (bf162*)pyh, (bf162*)pyl, n2x);
    const dim3 gg(N_EMBD / 128, MROWS / 128);
    gemm_out_mma<<<gg, 256>>>(pyh, pyl, bo, out);
}

// round 7
// speedup vs baseline: 2.2346x; 1.5077x over previous
#include <cuda_runtime.h>
#include <cuda_bf16.h>
#include <cstdint>
#include <cstddef>

// ---------------------------------------------------------------------------
// LatentAttention v4: B=2, T=2048, n_embd=1024, heads=16, latent=64
//   - 4 big GEMMs on tensor cores, bf16x3 split (unchanged from v3)
//   - flash attention NOW on tensor cores too (bf16x3 QK^T and PV,
//     fp32 softmax, FA2 register-resident P)
// ---------------------------------------------------------------------------

#define N_EMBD   1024
#define N_HEADS  16
#define LATENT   64
#define BATCH    2
#define SEQ      2048
#define MROWS    (BATCH * SEQ)          // 4096
#define KDIM     1024
#define ATT_SCALE 0.125f

typedef __nv_bfloat16  bf16;
typedef __nv_bfloat162 bf162;

// ------------------------- device scratch ----------------------------------
__device__ float g_Wqc[N_EMBD * N_EMBD];
__device__ float g_bqc[N_EMBD];
__device__ float g_qkv[3 * MROWS * N_EMBD];     // [qc | k | v] fp32
__device__ float g_y  [MROWS * N_EMBD];         // attention output fp32

__device__ bf16  g_xs_hi[MROWS * N_EMBD];
__device__ bf16  g_xs_lo[MROWS * N_EMBD];
__device__ bf16  g_ys_hi[MROWS * N_EMBD];
__device__ bf16  g_ys_lo[MROWS * N_EMBD];
__device__ bf16  g_wt_hi[4][N_EMBD * N_EMBD];   // 0=Wqc 1=Wk 2=Wv 3=Wo, [N][K]
__device__ bf16  g_wt_lo[4][N_EMBD * N_EMBD];

// ---------------------------------------------------------------------------
__global__ void build_wqc(const float* __restrict__ Wq,
                          const float* __restrict__ Wc,
                          const float* __restrict__ bq,
                          float* __restrict__ Wqc,
                          float* __restrict__ bqc)
{
    int idx = blockIdx.x * blockDim.x + threadIdx.x;
    int c   = idx >> 10;
    int col = idx & 1023;
    int h   = col >> 6;
    int l   = col & 63;
    const float* wrow = &Wq[(size_t)c * N_EMBD + h * LATENT];
    float s = 0.f;
#pragma unroll 8
    for (int d = 0; d < LATENT; d++)
        s += wrow[d] * Wc[d * LATENT + l];
    Wqc[idx] = s;
    if (c == 0) {
        float sb = 0.f;
#pragma unroll 8
        for (int d = 0; d < LATENT; d++)
            sb += bq[h * LATENT + d] * Wc[d * LATENT + l];
        bqc[col] = sb;
    }
}

__global__ void split2(const float* __restrict__ src,
                       bf162* __restrict__ hi, bf162* __restrict__ lo, int n2)
{
    int i = blockIdx.x * blockDim.x + threadIdx.x;
    if (i >= n2) return;
    const float2 v = reinterpret_cast<const float2*>(src)[i];
    bf16 h0 = __float2bfloat16(v.x);
    bf16 h1 = __float2bfloat16(v.y);
    bf16 l0 = __float2bfloat16(v.x - __bfloat162float(h0));
    bf16 l1 = __float2bfloat16(v.y - __bfloat162float(h1));
    hi[i] = bf162(h0, h1);
    lo[i] = bf162(l0, l1);
}

__global__ void tsplit(const float* __restrict__ W,
                       bf16* __restrict__ Th, bf16* __restrict__ Tl)
{
    __shared__ float t[32][33];
    const int tx = threadIdx.x, ty = threadIdx.y;
    const int n0 = blockIdx.x * 32, k0 = blockIdx.y * 32;
#pragma unroll
    for (int i = 0; i < 4; i++)
        t[ty + 8 * i][tx] = W[(size_t)(k0 + ty + 8 * i) * N_EMBD + n0 + tx];
    __syncthreads();
#pragma unroll
    for (int i = 0; i < 4; i++) {
        const int n = n0 + ty + 8 * i;
        const int k = k0 + tx;
        const float v = t[tx][ty + 8 * i];
        bf16 h = __float2bfloat16(v);
        bf16 l = __float2bfloat16(v - __bfloat162float(h));
        Th[(size_t)n * KDIM + k] = h;
        Tl[(size_t)n * KDIM + k] = l;
    }
}

// ---------------------------------------------------------------------------
// bf16 m16n8k16 mma
// ---------------------------------------------------------------------------
__device__ __forceinline__
void mma_bf16(float& d0, float& d1, float& d2, float& d3,
              uint32_t a0, uint32_t a1, uint32_t a2, uint32_t a3,
              uint32_t b0, uint32_t b1)
{
    asm volatile(
        "mma.sync.aligned.m16n8k16.row.col.f32.bf16.bf16.f32 "
        "{%0,%1,%2,%3}, {%4,%5,%6,%7}, {%8,%9}, {%0,%1,%2,%3};\n"
        : "+f"(d0), "+f"(d1), "+f"(d2), "+f"(d3)
        : "r"(a0), "r"(a1), "r"(a2), "r"(a3), "r"(b0), "r"(b1));
}

// split a float pair into packed bf16 hi / lo words (low 16 bits = first elem)
__device__ __forceinline__
void split_pack(float x, float y, uint32_t& hi, uint32_t& lo)
{
    bf162 h = __floats2bfloat162_rn(x, y);
    bf162 l = __floats2bfloat162_rn(x - __bfloat162float(h.x),
                                    y - __bfloat162float(h.y));
    hi = *reinterpret_cast<uint32_t*>(&h);
    lo = *reinterpret_cast<uint32_t*>(&l);
}

// ---------------------------------------------------------------------------
// GEMM bf16x3 body (unchanged from v3)
// ---------------------------------------------------------------------------
#define SMW 20

__device__ __forceinline__
void gemm3_body(const bf16* __restrict__ Ah, const bf16* __restrict__ Al,
                const bf16* __restrict__ Bh, const bf16* __restrict__ Bl,
                const float* __restrict__ bias, float* __restrict__ C,
                int M, int N, int K, int bx, int by)
{
    __shared__ __align__(16) uint32_t sAh[128][SMW];
    __shared__ __align__(16) uint32_t sAl[128][SMW];
    __shared__ __align__(16) uint32_t sBh[128][SMW];
    __shared__ __align__(16) uint32_t sBl[128][SMW];

    const int tid    = threadIdx.x;
    const int lane   = tid & 31;
    const int wid    = tid >> 5;
    const int warp_m = wid >> 2;
    const int warp_n = wid & 3;
    const int m0     = by * 128;
    const int n0     = bx * 128;
    const int lg     = lane >> 2;
    const int lc     = lane & 3;

    float acc[4][4][4];
#pragma unroll
    for (int i = 0; i < 4; i++)
#pragma unroll
        for (int j = 0; j < 4; j++)
#pragma unroll
            for (int c = 0; c < 4; c++) acc[i][j][c] = 0.f;

    for (int k0 = 0; k0 < K; k0 += 32) {
        __syncthreads();
#pragma unroll
        for (int it = 0; it < 2; it++) {
            const int idx = tid + it * 256;
            const int row = idx >> 2;
            const int q   = idx & 3;
            const size_t ga = (size_t)(m0 + row) * K + k0 + q * 8;
            const size_t gb = (size_t)(n0 + row) * K + k0 + q * 8;
            *reinterpret_cast<float4*>(&sAh[row][q * 4]) =
                *reinterpret_cast<const float4*>(Ah + ga);
            *reinterpret_cast<float4*>(&sAl[row][q * 4]) =
                *reinterpret_cast<const float4*>(Al + ga);
            *reinterpret_cast<float4*>(&sBh[row][q * 4]) =
                *reinterpret_cast<const float4*>(Bh + gb);
            *reinterpret_cast<float4*>(&sBl[row][q * 4]) =
                *reinterpret_cast<const float4*>(Bl + gb);
        }
        __syncthreads();

#pragma unroll
        for (int ks = 0; ks < 2; ks++) {
            const int kw = ks * 8;
            uint32_t bh[4][2], bl[4][2];
#pragma unroll
            for (int j = 0; j < 4; j++) {
                const int n = warp_n * 32 + j * 8 + lg;
                bh[j][0] = sBh[n][kw + lc];
                bh[j][1] = sBh[n][kw + 4 + lc];
                bl[j][0] = sBl[n][kw + lc];
                bl[j][1] = sBl[n][kw + 4 + lc];
            }
#pragma unroll
            for (int i = 0; i < 4; i++) {
                const int r = warp_m * 64 + i * 16 + lg;
                uint32_t ah0 = sAh[r][kw + lc];
                uint32_t ah1 = sAh[r + 8][kw + lc];
                uint32_t ah2 = sAh[r][kw + 4 + lc];
                uint32_t ah3 = sAh[r + 8][kw + 4 + lc];
                uint32_t al0 = sAl[r][kw + lc];
                uint32_t al1 = sAl[r + 8][kw + lc];
                uint32_t al2 = sAl[r][kw + 4 + lc];
                uint32_t al3 = sAl[r + 8][kw + 4 + lc];
#pragma unroll
                for (int j = 0; j < 4; j++) {
                    float* d = acc[i][j];
                    mma_bf16(d[0], d[1], d[2], d[3], ah0, ah1, ah2, ah3,
                             bh[j][0], bh[j][1]);
                    mma_bf16(d[0], d[1], d[2], d[3], ah0, ah1, ah2, ah3,
                             bl[j][0], bl[j][1]);
                    mma_bf16(d[0], d[1], d[2], d[3], al0, al1, al2, al3,
                             bh[j][0], bh[j][1]);
                }
            }
        }
    }

#pragma unroll
    for (int j = 0; j < 4; j++) {
        const int cn = n0 + warp_n * 32 + j * 8 + 2 * lc;
        const float2 bb = *reinterpret_cast<const float2*>(&bias[cn]);
#pragma unroll
        for (int i = 0; i < 4; i++) {
            const int r0 = m0 + warp_m * 64 + i * 16 + lg;
            float2 o0 = make_float2(acc[i][j][0] + bb.x, acc[i][j][1] + bb.y);
            float2 o1 = make_float2(acc[i][j][2] + bb.x, acc[i][j][3] + bb.y);
            *reinterpret_cast<float2*>(&C[(size_t)r0 * N + cn])       = o0;
            *reinterpret_cast<float2*>(&C[(size_t)(r0 + 8) * N + cn]) = o1;
        }
    }
}

__global__ __launch_bounds__(256)
void gemm_qkv_mma(const bf16* __restrict__ xh, const bf16* __restrict__ xl,
                  const float* __restrict__ bqc,
                  const float* __restrict__ bk,
                  const float* __restrict__ bv,
                  float* __restrict__ Cqkv)
{
    const int z = blockIdx.z;
    const bf16* Bh = g_wt_hi[z];
    const bf16* Bl = g_wt_lo[z];
    const float* b = (z == 0) ? bqc : (z == 1) ? bk : bv;
    float* C = Cqkv + (size_t)z * MROWS * N_EMBD;
    gemm3_body(xh, xl, Bh, Bl, b, C, MROWS, N_EMBD, KDIM,
               blockIdx.x, blockIdx.y);
}

__global__ __launch_bounds__(256)
void gemm_out_mma(const bf16* __restrict__ yh, const bf16* __restrict__ yl,
                  const float* __restrict__ bo, float* __restrict__ C)
{
    gemm3_body(yh, yl, g_wt_hi[3], g_wt_lo[3], bo, C, MROWS, N_EMBD, KDIM,
               blockIdx.x, blockIdx.y);
}

// ---------------------------------------------------------------------------
// Flash attention v4 — tensor cores, bf16x3 for QK^T and PV.
// Block: 256 threads = 8 warps; 128 q-rows (16/warp), 64-key tiles.
// Q frags in registers (scale folded in).  K natural [key][lat], V transposed
// [lat][key] in smem, hi/lo split, rows padded to FW=36 words (conflict-free).
// S fragment -> (exp) -> packed bf16 pairs = A operand of PV (FA2 style).
// ---------------------------------------------------------------------------
#define FW 36    // smem row stride in 32-bit words

__global__ __launch_bounds__(256)
void flash_mma(const float* __restrict__ Qg,
               const float* __restrict__ Kg,
               const float* __restrict__ Vg,
               float* __restrict__ Yg)
{
    __shared__ uint32_t sKh[64][FW];   // [key][lat-pair]
    __shared__ uint32_t sKl[64][FW];
    __shared__ uint32_t sVh[64][FW];   // [lat][key-pair] (transposed)
    __shared__ uint32_t sVl[64][FW];

    const int tid  = threadIdx.x;
    const int lane = tid & 31;
    const int wid  = tid >> 5;          // 0..7, warp owns q-rows wid*16..+15
    const int g    = lane >> 2;         // 0..7
    const int c    = lane & 3;          // 0..3
    const int qb   = gridDim.x - 1 - blockIdx.x;   // long blocks first
    const int bh   = blockIdx.y;
    const int b    = bh >> 4;
    const int h    = bh & 15;
    const size_t base = (size_t)b * SEQ * N_EMBD + (size_t)h * LATENT;

    const int r0 = qb * 128 + wid * 16 + g;   // global q row (d0,d1)
    const int r1 = r0 + 8;                    // global q row (d2,d3)

    // ---- load Q fragments into registers, scaled by ATT_SCALE, hi/lo split
    uint32_t qh[4][4], ql[4][4];              // [ks][areg]
#pragma unroll
    for (int ks = 0; ks < 4; ks++) {
        const int k0a = 16 * ks + 2 * c;
        const int k0b = k0a + 8;
        float2 f0 = *reinterpret_cast<const float2*>(&Qg[base + (size_t)r0 * N_EMBD + k0a]);
        float2 f1 = *reinterpret_cast<const float2*>(&Qg[base + (size_t)r1 * N_EMBD + k0a]);
        float2 f2 = *reinterpret_cast<const float2*>(&Qg[base + (size_t)r0 * N_EMBD + k0b]);
        float2 f3 = *reinterpret_cast<const float2*>(&Qg[base + (size_t)r1 * N_EMBD + k0b]);
        split_pack(f0.x * ATT_SCALE, f0.y * ATT_SCALE, qh[ks][0], ql[ks][0]);
        split_pack(f1.x * ATT_SCALE, f1.y * ATT_SCALE, qh[ks][1], ql[ks][1]);
        split_pack(f2.x * ATT_SCALE, f2.y * ATT_SCALE, qh[ks][2], ql[ks][2]);
        split_pack(f3.x * ATT_SCALE, f3.y * ATT_SCALE, qh[ks][3], ql[ks][3]);
    }

    // ---- softmax state + output accumulators
    float m0 = -1e30f, m1 = -1e30f, l0 = 0.f, l1 = 0.f;
    float O[8][4];
#pragma unroll
    for (int j = 0; j < 8; j++)
#pragma unroll
        for (int t = 0; t < 4; t++) O[j][t] = 0.f;

    const int jmax = 2 * qb + 1;
    for (int jb = 0; jb <= jmax; jb++) {
        __syncthreads();   // prior tile's mma reads of sK/sV done
        // ---- load K (natural) + V (transposed) tiles, bf16 hi/lo
#pragma unroll
        for (int it = 0; it < 4; it++) {
            const int idx  = tid + it * 256;       // 0..1023
            const int key  = idx >> 4;             // 0..63
            const int latw = (idx & 15) * 4;       // lat base of float4
            const size_t goff = base + (size_t)(jb * 64 + key) * N_EMBD + latw;
            const float4 kv = *reinterpret_cast<const float4*>(&Kg[goff]);
            uint32_t h0, l0w, h1, l1w;
            split_pack(kv.x, kv.y, h0, l0w);
            split_pack(kv.z, kv.w, h1, l1w);
            const int w = latw >> 1;               // word index (even)
            sKh[key][w] = h0; sKh[key][w + 1] = h1;
            sKl[key][w] = l0w; sKl[key][w + 1] = l1w;

            const float4 vv = *reinterpret_cast<const float4*>(&Vg[goff]);
            bf16* vhp = reinterpret_cast<bf16*>(&sVh[0][0]);
            bf16* vlp = reinterpret_cast<bf16*>(&sVl[0][0]);
            const float ve[4] = {vv.x, vv.y, vv.z, vv.w};
#pragma unroll
            for (int e = 0; e < 4; e++) {
                bf16 vh = __float2bfloat16(ve[e]);
                bf16 vl = __float2bfloat16(ve[e] - __bfloat162float(vh));
                vhp[(latw + e) * (2 * FW) + key] = vh;
                vlp[(latw + e) * (2 * FW) + key] = vl;
            }
        }
        __syncthreads();

        // ---- S = Q . K^T (scaled), bf16x3
        float S[8][4];
#pragma unroll
        for (int j = 0; j < 8; j++)
#pragma unroll
            for (int t = 0; t < 4; t++) S[j][t] = 0.f;

#pragma unroll
        for (int ks = 0; ks < 4; ks++) {
#pragma unroll
            for (int j = 0; j < 8; j++) {
                const int key = 8 * j + g;
                const uint32_t bh0 = sKh[key][8 * ks + c];
                const uint32_t bh1 = sKh[key][8 * ks + 4 + c];
                const uint32_t bl0 = sKl[key][8 * ks + c];
                const uint32_t bl1 = sKl[key][8 * ks + 4 + c];
                float* d = S[j];
                mma_bf16(d[0], d[1], d[2], d[3],
                         qh[ks][0], qh[ks][1], qh[ks][2], qh[ks][3], bh0, bh1);
                mma_bf16(d[0], d[1], d[2], d[3],
                         qh[ks][0], qh[ks][1], qh[ks][2], qh[ks][3], bl0, bl1);
                mma_bf16(d[0], d[1], d[2], d[3],
                         ql[ks][0], ql[ks][1], ql[ks][2], ql[ks][3], bh0, bh1);
            }
        }

        // ---- causal mask (diagonal region only)
        if (jb >= 2 * qb) {
#pragma unroll
            for (int j = 0; j < 8; j++) {
                const int col = jb * 64 + 8 * j + 2 * c;
                if (col     > r0) S[j][0] = -1e30f;
                if (col + 1 > r0) S[j][1] = -1e30f;
                if (col     > r1) S[j][2] = -1e30f;
                if (col + 1 > r1) S[j][3] = -1e30f;
            }
        }

        // ---- online softmax (rows r0, r1); quad lanes share rows
        float mx0 = -1e30f, mx1 = -1e30f;
#pragma unroll
        for (int j = 0; j < 8; j++) {
            mx0 = fmaxf(mx0, fmaxf(S[j][0], S[j][1]));
            mx1 = fmaxf(mx1, fmaxf(S[j][2], S[j][3]));
        }
        mx0 = fmaxf(mx0, __shfl_xor_sync(0xffffffffu, mx0, 1));
        mx0 = fmaxf(mx0, __shfl_xor_sync(0xffffffffu, mx0, 2));
        mx1 = fmaxf(mx1, __shfl_xor_sync(0xffffffffu, mx1, 1));
        mx1 = fmaxf(mx1, __shfl_xor_sync(0xffffffffu, mx1, 2));

        const float mn0 = fmaxf(m0, mx0);
        const float mn1 = fmaxf(m1, mx1);
        const float a0  = __expf(m0 - mn0);
        const float a1  = __expf(m1 - mn1);
        m0 = mn0; m1 = mn1;

        float rs0 = 0.f, rs1 = 0.f;
#pragma unroll
        for (int j = 0; j < 8; j++) {
            S[j][0] = __expf(S[j][0] - mn0);
            S[j][1] = __expf(S[j][1] - mn0);
            S[j][2] = __expf(S[j][2] - mn1);
            S[j][3] = __expf(S[j][3] - mn1);
            rs0 += S[j][0] + S[j][1];
            rs1 += S[j][2] + S[j][3];
        }
        rs0 += __shfl_xor_sync(0xffffffffu, rs0, 1);
        rs0 += __shfl_xor_sync(0xffffffffu, rs0, 2);
        rs1 += __shfl_xor_sync(0xffffffffu, rs1, 1);
        rs1 += __shfl_xor_sync(0xffffffffu, rs1, 2);
        l0 = l0 * a0 + rs0;
        l1 = l1 * a1 + rs1;

#pragma unroll
        for (int j = 0; j < 8; j++) {
            O[j][0] *= a0; O[j][1] *= a0;
            O[j][2] *= a1; O[j][3] *= a1;
        }

        // ---- O += P . V   (P = S frags repacked as A operands, bf16x3)
#pragma unroll
        for (int t = 0; t < 4; t++) {
            uint32_t ph0, pl0, ph1, pl1, ph2, pl2, ph3, pl3;
            split_pack(S[2 * t][0],     S[2 * t][1],     ph0, pl0);
            split_pack(S[2 * t][2],     S[2 * t][3],     ph1, pl1);
            split_pack(S[2 * t + 1][0], S[2 * t + 1][1], ph2, pl2);
            split_pack(S[2 * t + 1][2], S[2 * t + 1][3], ph3, pl3);
#pragma unroll
            for (int j = 0; j < 8; j++) {
                const int lat = 8 * j + g;
                const uint32_t bh0 = sVh[lat][8 * t + c];
                const uint32_t bh1 = sVh[lat][8 * t + 4 + c];
                const uint32_t bl0 = sVl[lat][8 * t + c];
                const uint32_t bl1 = sVl[lat][8 * t + 4 + c];
                float* d = O[j];
                mma_bf16(d[0], d[1], d[2], d[3], ph0, ph1, ph2, ph3, bh0, bh1);
                mma_bf16(d[0], d[1], d[2], d[3], ph0, ph1, ph2, ph3, bl0, bl1);
                mma_bf16(d[0], d[1], d[2], d[3], pl0, pl1, pl2, pl3, bh0, bh1);
            }
        }
    }

    // ---- normalize + write y
    const float i0 = 1.f / l0;
    const float i1 = 1.f / l1;
#pragma unroll
    for (int j = 0; j < 8; j++) {
        const int col = 8 * j + 2 * c;
        float2 o0 = make_float2(O[j][0] * i0, O[j][1] * i0);
        float2 o1 = make_float2(O[j][2] * i1, O[j][3] * i1);
        *reinterpret_cast<float2*>(&Yg[base + (size_t)r0 * N_EMBD + col]) = o0;
        *reinterpret_cast<float2*>(&Yg[base + (size_t)r1 * N_EMBD + col]) = o1;
    }
}

// ---------------------------------------------------------------------------
// Launcher. Inputs: x,Wq,bq,Wk,bk,Wv,bv,Wo,bo,Wc
// ---------------------------------------------------------------------------
extern "C" void kernel_launch(void* const* d_in, const int* in_sizes, int n_in,
                              void* d_out, int out_size)
{
    const float* x  = (const float*)d_in[0];
    const float* Wq = (const float*)d_in[1];
    const float* bq = (const float*)d_in[2];
    const float* Wk = (const float*)d_in[3];
    const float* bk = (const float*)d_in[4];
    const float* Wv = (const float*)d_in[5];
    const float* bv = (const float*)d_in[6];
    const float* Wo = (const float*)d_in[7];
    const float* bo = (const float*)d_in[8];
    const float* Wc = (const float*)d_in[9];
    float* out = (float*)d_out;

    float *pWqc, *pbqc, *pqkv, *py;
    bf16 *pxh, *pxl, *pyh, *pyl, *pwh, *pwl;
    cudaGetSymbolAddress((void**)&pWqc, g_Wqc);
    cudaGetSymbolAddress((void**)&pbqc, g_bqc);
    cudaGetSymbolAddress((void**)&pqkv, g_qkv);
    cudaGetSymbolAddress((void**)&py,   g_y);
    cudaGetSymbolAddress((void**)&pxh,  g_xs_hi);
    cudaGetSymbolAddress((void**)&pxl,  g_xs_lo);
    cudaGetSymbolAddress((void**)&pyh,  g_ys_hi);
    cudaGetSymbolAddress((void**)&pyl,  g_ys_lo);
    cudaGetSymbolAddress((void**)&pwh,  g_wt_hi);
    cudaGetSymbolAddress((void**)&pwl,  g_wt_lo);

    float* pqc = pqkv;
    float* pk  = pqkv + (size_t)MROWS * N_EMBD;
    float* pv  = pqkv + (size_t)2 * MROWS * N_EMBD;

    // --- prep -----------------------------------------------------------------
    build_wqc<<<4096, 256>>>(Wq, Wc, bq, pWqc, pbqc);

    const int n2x = MROWS * N_EMBD / 2;
    split2<<<(n2x + 255) / 256, 256>>>(x, (bf162*)pxh, (bf162*)pxl, n2x);

    const dim3 tg(N_EMBD / 32, N_EMBD / 32);
    const dim3 tb(32, 8);
    const size_t WSZ = (size_t)N_EMBD * N_EMBD;
    tsplit<<<tg, tb>>>(pWqc, pwh + 0 * WSZ, pwl + 0 * WSZ);
    tsplit<<<tg, tb>>>(Wk,   pwh + 1 * WSZ, pwl + 1 * WSZ);
    tsplit<<<tg, tb>>>(Wv,   pwh + 2 * WSZ, pwl + 2 * WSZ);
    tsplit<<<tg, tb>>>(Wo,   pwh + 3 * WSZ, pwl + 3 * WSZ);

    // --- QKV projection (tensor cores) ----------------------------------------
    const dim3 gq(N_EMBD / 128, MROWS / 128, 3);
    gemm_qkv_mma<<<gq, 256>>>(pxh, pxl, pbqc, bk, bv, pqkv);

    // --- attention (tensor cores) ----------------------------------------------
    flash_mma<<<dim3(SEQ / 128, BATCH * N_HEADS), 256>>>(pqc, pk, pv, py);

    // --- output projection (tensor cores) ---------------------------------------
    split2<<<(n2x + 255) / 256, 256>>>(py, (bf162*)pyh, (bf162*)pyl, n2x);
    const dim3 gg(N_EMBD / 128, MROWS / 128);
    gemm_out_mma<<<gg, 256>>>(pyh, pyl, bo, out);
}

// round 8
// speedup vs baseline: 2.3854x; 1.0675x over previous
#include <cuda_runtime.h>
#include <cuda_bf16.h>
#include <cstdint>
#include <cstddef>

// ---------------------------------------------------------------------------
// LatentAttention v5: B=2, T=2048, n_embd=1024, heads=16, latent=64
//   - GEMMs: bf16x3 split, cp.async double-buffered stages, ldmatrix frags
//   - gemm_qkv writes bf16 hi/lo directly; flash reads/writes bf16 hi/lo
//   - flash attention: tensor-core bf16x3 (v4 core, new I/O)
// ---------------------------------------------------------------------------

#define N_EMBD   1024
#define N_HEADS  16
#define LATENT   64
#define BATCH    2
#define SEQ      2048
#define MROWS    (BATCH * SEQ)          // 4096
#define KDIM     1024

typedef __nv_bfloat16  bf16;
typedef __nv_bfloat162 bf162;

// ------------------------- device scratch ----------------------------------
__device__ float g_Wqc[N_EMBD * N_EMBD];
__device__ float g_bqc[N_EMBD];
__device__ bf16  g_qkvh[3 * MROWS * N_EMBD];    // [qc | k | v] hi
__device__ bf16  g_qkvl[3 * MROWS * N_EMBD];    // lo
__device__ bf16  g_xs_hi[MROWS * N_EMBD];
__device__ bf16  g_xs_lo[MROWS * N_EMBD];
__device__ bf16  g_ys_hi[MROWS * N_EMBD];
__device__ bf16  g_ys_lo[MROWS * N_EMBD];
__device__ bf16  g_wt_hi[4][N_EMBD * N_EMBD];   // 0=Wqc 1=Wk 2=Wv 3=Wo, [N][K]
__device__ bf16  g_wt_lo[4][N_EMBD * N_EMBD];

// ---------------------------------------------------------------------------
__global__ void build_wqc(const float* __restrict__ Wq,
                          const float* __restrict__ Wc,
                          const float* __restrict__ bq,
                          float* __restrict__ Wqc,
                          float* __restrict__ bqc)
{
    int idx = blockIdx.x * blockDim.x + threadIdx.x;
    int c   = idx >> 10;
    int col = idx & 1023;
    int h   = col >> 6;
    int l   = col & 63;
    const float* wrow = &Wq[(size_t)c * N_EMBD + h * LATENT];
    float s = 0.f;
#pragma unroll 8
    for (int d = 0; d < LATENT; d++)
        s += wrow[d] * Wc[d * LATENT + l];
    Wqc[idx] = s;
    if (c == 0) {
        float sb = 0.f;
#pragma unroll 8
        for (int d = 0; d < LATENT; d++)
            sb += bq[h * LATENT + d] * Wc[d * LATENT + l];
        bqc[col] = sb;
    }
}

__global__ void split2(const float* __restrict__ src,
                       bf162* __restrict__ hi, bf162* __restrict__ lo, int n2)
{
    int i = blockIdx.x * blockDim.x + threadIdx.x;
    if (i >= n2) return;
    const float2 v = reinterpret_cast<const float2*>(src)[i];
    bf16 h0 = __float2bfloat16(v.x);
    bf16 h1 = __float2bfloat16(v.y);
    bf16 l0 = __float2bfloat16(v.x - __bfloat162float(h0));
    bf16 l1 = __float2bfloat16(v.y - __bfloat162float(h1));
    hi[i] = bf162(h0, h1);
    lo[i] = bf162(l0, l1);
}

__global__ void tsplit(const float* __restrict__ W,
                       bf16* __restrict__ Th, bf16* __restrict__ Tl)
{
    __shared__ float t[32][33];
    const int tx = threadIdx.x, ty = threadIdx.y;
    const int n0 = blockIdx.x * 32, k0 = blockIdx.y * 32;
#pragma unroll
    for (int i = 0; i < 4; i++)
        t[ty + 8 * i][tx] = W[(size_t)(k0 + ty + 8 * i) * N_EMBD + n0 + tx];
    __syncthreads();
#pragma unroll
    for (int i = 0; i < 4; i++) {
        const int n = n0 + ty + 8 * i;
        const int k = k0 + tx;
        const float v = t[tx][ty + 8 * i];
        bf16 h = __float2bfloat16(v);
        bf16 l = __float2bfloat16(v - __bfloat162float(h));
        Th[(size_t)n * KDIM + k] = h;
        Tl[(size_t)n * KDIM + k] = l;
    }
}

// ---------------------------------------------------------------------------
// primitives
// ---------------------------------------------------------------------------
__device__ __forceinline__
void mma_bf16(float& d0, float& d1, float& d2, float& d3,
              uint32_t a0, uint32_t a1, uint32_t a2, uint32_t a3,
              uint32_t b0, uint32_t b1)
{
    asm volatile(
        "mma.sync.aligned.m16n8k16.row.col.f32.bf16.bf16.f32 "
        "{%0,%1,%2,%3}, {%4,%5,%6,%7}, {%8,%9}, {%0,%1,%2,%3};\n"
        : "+f"(d0), "+f"(d1), "+f"(d2), "+f"(d3)
        : "r"(a0), "r"(a1), "r"(a2), "r"(a3), "r"(b0), "r"(b1));
}

__device__ __forceinline__
void split_pack(float x, float y, uint32_t& hi, uint32_t& lo)
{
    bf162 h = __floats2bfloat162_rn(x, y);
    bf162 l = __floats2bfloat162_rn(x - __bfloat162float(h.x),
                                    y - __bfloat162float(h.y));
    hi = *reinterpret_cast<uint32_t*>(&h);
    lo = *reinterpret_cast<uint32_t*>(&l);
}

__device__ __forceinline__ void cp16(uint32_t d, const void* s) {
    asm volatile("cp.async.cg.shared.global [%0], [%1], 16;" :: "r"(d), "l"(s));
}
__device__ __forceinline__ void cp_commit() {
    asm volatile("cp.async.commit_group;");
}
__device__ __forceinline__ void cp_wait1() {
    asm volatile("cp.async.wait_group 1;");
}
__device__ __forceinline__
void ldsm4(uint32_t& r0, uint32_t& r1, uint32_t& r2, uint32_t& r3, uint32_t a) {
    asm volatile("ldmatrix.sync.aligned.m8n8.x4.shared.b16 {%0,%1,%2,%3}, [%4];"
                 : "=r"(r0), "=r"(r1), "=r"(r2), "=r"(r3) : "r"(a));
}

// ---------------------------------------------------------------------------
// GEMM bf16x3 v2: 128x128 tile, BK=32, 8 warps (2m x 4n), cp.async 2-stage,
// ldmatrix fragment loads.  SMW=20-word row stride: ldmatrix conflict-free.
// ---------------------------------------------------------------------------
#define SMW 20
#define GST (128 * SMW)            // words per array per stage
#define GSTAGE (4 * GST)           // words per stage
#define GEMM_SMEM (2 * GSTAGE * 4) // 81920 bytes

template<bool SPLIT_OUT>
__device__ __forceinline__
void gemm3_body(const bf16* __restrict__ Ah_, const bf16* __restrict__ Al_,
                const bf16* __restrict__ Bh_, const bf16* __restrict__ Bl_,
                const float* __restrict__ bias,
                float* __restrict__ C, bf16* __restrict__ Ch, bf16* __restrict__ Cl,
                int N, int K, int bx, int by)
{
    extern __shared__ uint32_t gsm[];
    const int tid    = threadIdx.x;
    const int lane   = tid & 31;
    const int wid    = tid >> 5;
    const int warp_m = wid >> 2;
    const int warp_n = wid & 3;
    const int m0     = by * 128;
    const int n0     = bx * 128;
    const int lg     = lane >> 2;
    const int lc     = lane & 3;
    const uint32_t sbase = (uint32_t)__cvta_generic_to_shared(gsm);

    float acc[4][4][4];
#pragma unroll
    for (int i = 0; i < 4; i++)
#pragma unroll
        for (int j = 0; j < 4; j++)
#pragma unroll
            for (int c = 0; c < 4; c++) acc[i][j][c] = 0.f;

    const int KT = K >> 5;

    // issue one stage of cp.async loads (8 x 16B per thread)
    auto load_stage = [&](int s, int kb) {
        const uint32_t dst0 = sbase + (uint32_t)(s * GSTAGE * 4);
#pragma unroll
        for (int arr = 0; arr < 4; arr++) {
            const bf16* src = (arr == 0) ? Ah_ : (arr == 1) ? Al_
                            : (arr == 2) ? Bh_ : Bl_;
            const int rbase = (arr < 2) ? m0 : n0;
#pragma unroll
            for (int it = 0; it < 2; it++) {
                const int sub = tid + it * 256;      // 0..511
                const int row = sub >> 2;            // 0..127
                const int q   = sub & 3;             // 16B chunk
                cp16(dst0 + (uint32_t)((arr * GST + row * SMW + q * 4) * 4),
                     src + (size_t)(rbase + row) * K + kb + q * 8);
            }
        }
        cp_commit();
    };

    load_stage(0, 0);
    load_stage(1, 32);

    const int arow = lane & 15;
    const int acol = (lane & 16) ? 4 : 0;
    const int brow = (lane & 7) + ((lane & 16) ? 8 : 0);
    const int bcol = (lane & 8) ? 4 : 0;

    for (int kt = 0; kt < KT; kt++) {
        cp_wait1();
        __syncthreads();
        const uint32_t st    = sbase + (uint32_t)((kt & 1) * GSTAGE * 4);
        const uint32_t offAh = st;
        const uint32_t offAl = st + GST * 4;
        const uint32_t offBh = st + 2 * GST * 4;
        const uint32_t offBl = st + 3 * GST * 4;

#pragma unroll
        for (int ks = 0; ks < 2; ks++) {
            const int kw = ks * 8;
            uint32_t bh[8], bl[8];
#pragma unroll
            for (int jp = 0; jp < 2; jp++) {
                const int rB = warp_n * 32 + jp * 16 + brow;
                const uint32_t off = (uint32_t)((rB * SMW + kw + bcol) * 4);
                ldsm4(bh[jp*4+0], bh[jp*4+1], bh[jp*4+2], bh[jp*4+3], offBh + off);
                ldsm4(bl[jp*4+0], bl[jp*4+1], bl[jp*4+2], bl[jp*4+3], offBl + off);
            }
#pragma unroll
            for (int i = 0; i < 4; i++) {
                const int rA = warp_m * 64 + i * 16 + arow;
                const uint32_t off = (uint32_t)((rA * SMW + kw + acol) * 4);
                uint32_t ah0, ah1, ah2, ah3, al0, al1, al2, al3;
                ldsm4(ah0, ah1, ah2, ah3, offAh + off);
                ldsm4(al0, al1, al2, al3, offAl + off);
#pragma unroll
                for (int j = 0; j < 4; j++) {
                    const int bi = (j >> 1) * 4 + (j & 1) * 2;
                    float* d = acc[i][j];
                    mma_bf16(d[0], d[1], d[2], d[3],
                             ah0, ah1, ah2, ah3, bh[bi], bh[bi+1]);
                    mma_bf16(d[0], d[1], d[2], d[3],
                             ah0, ah1, ah2, ah3, bl[bi], bl[bi+1]);
                    mma_bf16(d[0], d[1], d[2], d[3],
                             al0, al1, al2, al3, bh[bi], bh[bi+1]);
                }
            }
        }
        __syncthreads();
        if (kt + 2 < KT) load_stage(kt & 1, (kt + 2) * 32);
        else             cp_commit();    // empty group keeps wait-count exact
    }

    // epilogue
#pragma unroll
    for (int j = 0; j < 4; j++) {
        const int cn = n0 + warp_n * 32 + j * 8 + 2 * lc;
        const float2 bb = *reinterpret_cast<const float2*>(&bias[cn]);
#pragma unroll
        for (int i = 0; i < 4; i++) {
            const int r = m0 + warp_m * 64 + i * 16 + lg;
            const float v0 = acc[i][j][0] + bb.x, v1 = acc[i][j][1] + bb.y;
            const float v2 = acc[i][j][2] + bb.x, v3 = acc[i][j][3] + bb.y;
            if (SPLIT_OUT) {
                uint32_t h, l;
                split_pack(v0, v1, h, l);
                *reinterpret_cast<uint32_t*>(Ch + (size_t)r * N + cn) = h;
                *reinterpret_cast<uint32_t*>(Cl + (size_t)r * N + cn) = l;
                split_pack(v2, v3, h, l);
                *reinterpret_cast<uint32_t*>(Ch + (size_t)(r + 8) * N + cn) = h;
                *reinterpret_cast<uint32_t*>(Cl + (size_t)(r + 8) * N + cn) = l;
            } else {
                *reinterpret_cast<float2*>(&C[(size_t)r * N + cn]) =
                    make_float2(v0, v1);
                *reinterpret_cast<float2*>(&C[(size_t)(r + 8) * N + cn]) =
                    make_float2(v2, v3);
            }
        }
    }
}

__global__ __launch_bounds__(256, 2)
void gemm_qkv_mma(const bf16* __restrict__ xh, const bf16* __restrict__ xl,
                  const float* __restrict__ bqc,
                  const float* __restrict__ bk,
                  const float* __restrict__ bv,
                  bf16* __restrict__ qkvh, bf16* __restrict__ qkvl)
{
    const int z = blockIdx.z;
    const float* b = (z == 0) ? bqc : (z == 1) ? bk : bv;
    gemm3_body<true>(xh, xl, g_wt_hi[z], g_wt_lo[z], b, nullptr,
                     qkvh + (size_t)z * MROWS * N_EMBD,
                     qkvl + (size_t)z * MROWS * N_EMBD,
                     N_EMBD, KDIM, blockIdx.x, blockIdx.y);
}

__global__ __launch_bounds__(256, 2)
void gemm_out_mma(const bf16* __restrict__ yh, const bf16* __restrict__ yl,
                  const float* __restrict__ bo, float* __restrict__ C)
{
    gemm3_body<false>(yh, yl, g_wt_hi[3], g_wt_lo[3], bo, C, nullptr, nullptr,
                      N_EMBD, KDIM, blockIdx.x, blockIdx.y);
}

// ---------------------------------------------------------------------------
// Flash attention v5 — tensor cores, bf16x3; inputs/outputs pre-split bf16.
// 256 threads = 8 warps; 128 q-rows (16/warp), 64-key tiles.
// ---------------------------------------------------------------------------
#define FW 36    // smem row stride in 32-bit words

__device__ __forceinline__ uint32_t mul_eighth(uint32_t w)
{
    bf162 v = *reinterpret_cast<bf162*>(&w);
    const bf162 s = __floats2bfloat162_rn(0.125f, 0.125f);   // 2^-3: exact
    v = __hmul2(v, s);
    return *reinterpret_cast<uint32_t*>(&v);
}

__global__ __launch_bounds__(256)
void flash_mma(const bf16* __restrict__ Qh, const bf16* __restrict__ Ql,
               const bf16* __restrict__ Kh, const bf16* __restrict__ Kl,
               const bf16* __restrict__ Vh, const bf16* __restrict__ Vl,
               bf16* __restrict__ Yh, bf16* __restrict__ Yl)
{
    __shared__ uint32_t sKh[64][FW];   // [key][lat-pair]
    __shared__ uint32_t sKl[64][FW];
    __shared__ uint32_t sVh[64][FW];   // [lat][key-pair] (transposed)
    __shared__ uint32_t sVl[64][FW];

    const int tid  = threadIdx.x;
    const int lane = tid & 31;
    const int wid  = tid >> 5;
    const int g    = lane >> 2;
    const int c    = lane & 3;
    const int qb   = gridDim.x - 1 - blockIdx.x;   // long blocks first
    const int bh   = blockIdx.y;
    const int b    = bh >> 4;
    const int h    = bh & 15;
    const size_t base = (size_t)b * SEQ * N_EMBD + (size_t)h * LATENT;

    const int r0 = qb * 128 + wid * 16 + g;
    const int r1 = r0 + 8;

    // ---- Q fragments from pre-split arrays; fold in 1/8 scale (exact)
    uint32_t qh[4][4], ql[4][4];
#pragma unroll
    for (int ks = 0; ks < 4; ks++) {
        const int k0a = 16 * ks + 2 * c;
        const size_t e0 = base + (size_t)r0 * N_EMBD + k0a;
        const size_t e1 = base + (size_t)r1 * N_EMBD + k0a;
        qh[ks][0] = mul_eighth(*reinterpret_cast<const uint32_t*>(Qh + e0));
        qh[ks][1] = mul_eighth(*reinterpret_cast<const uint32_t*>(Qh + e1));
        qh[ks][2] = mul_eighth(*reinterpret_cast<const uint32_t*>(Qh + e0 + 8));
        qh[ks][3] = mul_eighth(*reinterpret_cast<const uint32_t*>(Qh + e1 + 8));
        ql[ks][0] = mul_eighth(*reinterpret_cast<const uint32_t*>(Ql + e0));
        ql[ks][1] = mul_eighth(*reinterpret_cast<const uint32_t*>(Ql + e1));
        ql[ks][2] = mul_eighth(*reinterpret_cast<const uint32_t*>(Ql + e0 + 8));
        ql[ks][3] = mul_eighth(*reinterpret_cast<const uint32_t*>(Ql + e1 + 8));
    }

    float m0 = -1e30f, m1 = -1e30f, l0 = 0.f, l1 = 0.f;
    float O[8][4];
#pragma unroll
    for (int j = 0; j < 8; j++)
#pragma unroll
        for (int t = 0; t < 4; t++) O[j][t] = 0.f;

    const int jmax = 2 * qb + 1;
    for (int jb = 0; jb <= jmax; jb++) {
        __syncthreads();
        // ---- load K (natural) + V (transposed) tiles, already-split bf16
#pragma unroll
        for (int it = 0; it < 4; it++) {
            const int idx = tid + it * 256;        // 0..1023
            const int key = idx >> 4;              // 0..63
            const int wq  = idx & 15;              // 4-lat group
            const size_t ge = base + (size_t)(jb * 64 + key) * N_EMBD + wq * 4;
            *reinterpret_cast<uint2*>(&sKh[key][wq * 2]) =
                *reinterpret_cast<const uint2*>(Kh + ge);
            *reinterpret_cast<uint2*>(&sKl[key][wq * 2]) =
                *reinterpret_cast<const uint2*>(Kl + ge);
            const uint2 vh2 = *reinterpret_cast<const uint2*>(Vh + ge);
            const uint2 vl2 = *reinterpret_cast<const uint2*>(Vl + ge);
            const bf16* vhe = reinterpret_cast<const bf16*>(&vh2);
            const bf16* vle = reinterpret_cast<const bf16*>(&vl2);
            bf16* vhp = reinterpret_cast<bf16*>(&sVh[0][0]);
            bf16* vlp = reinterpret_cast<bf16*>(&sVl[0][0]);
#pragma unroll
            for (int e = 0; e < 4; e++) {
                vhp[(wq * 4 + e) * (2 * FW) + key] = vhe[e];
                vlp[(wq * 4 + e) * (2 * FW) + key] = vle[e];
            }
        }
        __syncthreads();

        // ---- S = Q . K^T, bf16x3
        float S[8][4];
#pragma unroll
        for (int j = 0; j < 8; j++)
#pragma unroll
            for (int t = 0; t < 4; t++) S[j][t] = 0.f;

#pragma unroll
        for (int ks = 0; ks < 4; ks++) {
#pragma unroll
            for (int j = 0; j < 8; j++) {
                const int key = 8 * j + g;
                const uint32_t bh0 = sKh[key][8 * ks + c];
                const uint32_t bh1 = sKh[key][8 * ks + 4 + c];
                const uint32_t bl0 = sKl[key][8 * ks + c];
                const uint32_t bl1 = sKl[key][8 * ks + 4 + c];
                float* d = S[j];
                mma_bf16(d[0], d[1], d[2], d[3],
                         qh[ks][0], qh[ks][1], qh[ks][2], qh[ks][3], bh0, bh1);
                mma_bf16(d[0], d[1], d[2], d[3],
                         qh[ks][0], qh[ks][1], qh[ks][2], qh[ks][3], bl0, bl1);
                mma_bf16(d[0], d[1], d[2], d[3],
                         ql[ks][0], ql[ks][1], ql[ks][2], ql[ks][3], bh0, bh1);
            }
        }

        // ---- causal mask
        if (jb >= 2 * qb) {
#pragma unroll
            for (int j = 0; j < 8; j++) {
                const int col = jb * 64 + 8 * j + 2 * c;
                if (col     > r0) S[j][0] = -1e30f;
                if (col + 1 > r0) S[j][1] = -1e30f;
                if (col     > r1) S[j][2] = -1e30f;
                if (col + 1 > r1) S[j][3] = -1e30f;
            }
        }

        // ---- online softmax
        float mx0 = -1e30f, mx1 = -1e30f;
#pragma unroll
        for (int j = 0; j < 8; j++) {
            mx0 = fmaxf(mx0, fmaxf(S[j][0], S[j][1]));
            mx1 = fmaxf(mx1, fmaxf(S[j][2], S[j][3]));
        }
        mx0 = fmaxf(mx0, __shfl_xor_sync(0xffffffffu, mx0, 1));
        mx0 = fmaxf(mx0, __shfl_xor_sync(0xffffffffu, mx0, 2));
        mx1 = fmaxf(mx1, __shfl_xor_sync(0xffffffffu, mx1, 1));
        mx1 = fmaxf(mx1, __shfl_xor_sync(0xffffffffu, mx1, 2));

        const float mn0 = fmaxf(m0, mx0);
        const float mn1 = fmaxf(m1, mx1);
        const float a0  = __expf(m0 - mn0);
        const float a1  = __expf(m1 - mn1);
        m0 = mn0; m1 = mn1;

        float rs0 = 0.f, rs1 = 0.f;
#pragma unroll
        for (int j = 0; j < 8; j++) {
            S[j][0] = __expf(S[j][0] - mn0);
            S[j][1] = __expf(S[j][1] - mn0);
            S[j][2] = __expf(S[j][2] - mn1);
            S[j][3] = __expf(S[j][3] - mn1);
            rs0 += S[j][0] + S[j][1];
            rs1 += S[j][2] + S[j][3];
        }
        rs0 += __shfl_xor_sync(0xffffffffu, rs0, 1);
        rs0 += __shfl_xor_sync(0xffffffffu, rs0, 2);
        rs1 += __shfl_xor_sync(0xffffffffu, rs1, 1);
        rs1 += __shfl_xor_sync(0xffffffffu, rs1, 2);
        l0 = l0 * a0 + rs0;
        l1 = l1 * a1 + rs1;

#pragma unroll
        for (int j = 0; j < 8; j++) {
            O[j][0] *= a0; O[j][1] *= a0;
            O[j][2] *= a1; O[j][3] *= a1;
        }

        // ---- O += P . V  (bf16x3, P stays in registers)
#pragma unroll
        for (int t = 0; t < 4; t++) {
            uint32_t ph0, pl0, ph1, pl1, ph2, pl2, ph3, pl3;
            split_pack(S[2 * t][0],     S[2 * t][1],     ph0, pl0);
            split_pack(S[2 * t][2],     S[2 * t][3],     ph1, pl1);
            split_pack(S[2 * t + 1][0], S[2 * t + 1][1], ph2, pl2);
            split_pack(S[2 * t + 1][2], S[2 * t + 1][3], ph3, pl3);
#pragma unroll
            for (int j = 0; j < 8; j++) {
                const int lat = 8 * j + g;
                const uint32_t bh0 = sVh[lat][8 * t + c];
                const uint32_t bh1 = sVh[lat][8 * t + 4 + c];
                const uint32_t bl0 = sVl[lat][8 * t + c];
                const uint32_t bl1 = sVl[lat][8 * t + 4 + c];
                float* d = O[j];
                mma_bf16(d[0], d[1], d[2], d[3], ph0, ph1, ph2, ph3, bh0, bh1);
                mma_bf16(d[0], d[1], d[2], d[3], ph0, ph1, ph2, ph3, bl0, bl1);
                mma_bf16(d[0], d[1], d[2], d[3], pl0, pl1, pl2, pl3, bh0, bh1);
            }
        }
    }

    // ---- normalize + write y directly as hi/lo split
    const float i0 = 1.f / l0;
    const float i1 = 1.f / l1;
#pragma unroll
    for (int j = 0; j < 8; j++) {
        const int col = 8 * j + 2 * c;
        uint32_t h, l;
        split_pack(O[j][0] * i0, O[j][1] * i0, h, l);
        *reinterpret_cast<uint32_t*>(Yh + base + (size_t)r0 * N_EMBD + col) = h;
        *reinterpret_cast<uint32_t*>(Yl + base + (size_t)r0 * N_EMBD + col) = l;
        split_pack(O[j][2] * i1, O[j][3] * i1, h, l);
        *reinterpret_cast<uint32_t*>(Yh + base + (size_t)r1 * N_EMBD + col) = h;
        *reinterpret_cast<uint32_t*>(Yl + base + (size_t)r1 * N_EMBD + col) = l;
    }
}

// ---------------------------------------------------------------------------
// Launcher. Inputs: x,Wq,bq,Wk,bk,Wv,bv,Wo,bo,Wc
// ---------------------------------------------------------------------------
extern "C" void kernel_launch(void* const* d_in, const int* in_sizes, int n_in,
                              void* d_out, int out_size)
{
    const float* x  = (const float*)d_in[0];
    const float* Wq = (const float*)d_in[1];
    const float* bq = (const float*)d_in[2];
    const float* Wk = (const float*)d_in[3];
    const float* bk = (const float*)d_in[4];
    const float* Wv = (const float*)d_in[5];
    const float* bv = (const float*)d_in[6];
    const float* Wo = (const float*)d_in[7];
    const float* bo = (const float*)d_in[8];
    const float* Wc = (const float*)d_in[9];
    float* out = (float*)d_out;

    float *pWqc, *pbqc;
    bf16 *pqkvh, *pqkvl, *pxh, *pxl, *pyh, *pyl, *pwh, *pwl;
    cudaGetSymbolAddress((void**)&pWqc,  g_Wqc);
    cudaGetSymbolAddress((void**)&pbqc,  g_bqc);
    cudaGetSymbolAddress((void**)&pqkvh, g_qkvh);
    cudaGetSymbolAddress((void**)&pqkvl, g_qkvl);
    cudaGetSymbolAddress((void**)&pxh,   g_xs_hi);
    cudaGetSymbolAddress((void**)&pxl,   g_xs_lo);
    cudaGetSymbolAddress((void**)&pyh,   g_ys_hi);
    cudaGetSymbolAddress((void**)&pyl,   g_ys_lo);
    cudaGetSymbolAddress((void**)&pwh,   g_wt_hi);
    cudaGetSymbolAddress((void**)&pwl,   g_wt_lo);

    const size_t MN = (size_t)MROWS * N_EMBD;

    cudaFuncSetAttribute(gemm_qkv_mma,
                         cudaFuncAttributeMaxDynamicSharedMemorySize, GEMM_SMEM);
    cudaFuncSetAttribute(gemm_out_mma,
                         cudaFuncAttributeMaxDynamicSharedMemorySize, GEMM_SMEM);

    // --- prep -----------------------------------------------------------------
    build_wqc<<<4096, 256>>>(Wq, Wc, bq, pWqc, pbqc);

    const int n2x = MROWS * N_EMBD / 2;
    split2<<<(n2x + 255) / 256, 256>>>(x, (bf162*)pxh, (bf162*)pxl, n2x);

    const dim3 tg(N_EMBD / 32, N_EMBD / 32);
    const dim3 tb(32, 8);
    const size_t WSZ = (size_t)N_EMBD * N_EMBD;
    tsplit<<<tg, tb>>>(pWqc, pwh + 0 * WSZ, pwl + 0 * WSZ);
    tsplit<<<tg, tb>>>(Wk,   pwh + 1 * WSZ, pwl + 1 * WSZ);
    tsplit<<<tg, tb>>>(Wv,   pwh + 2 * WSZ, pwl + 2 * WSZ);
    tsplit<<<tg, tb>>>(Wo,   pwh + 3 * WSZ, pwl + 3 * WSZ);

    // --- QKV projection (writes split bf16 directly) ----------------------------
    const dim3 gq(N_EMBD / 128, MROWS / 128, 3);
    gemm_qkv_mma<<<gq, 256, GEMM_SMEM>>>(pxh, pxl, pbqc, bk, bv, pqkvh, pqkvl);

    // --- attention (consumes/produces split bf16) --------------------------------
    flash_mma<<<dim3(SEQ / 128, BATCH * N_HEADS), 256>>>(
        pqkvh, pqkvl,                        // Q
        pqkvh + MN, pqkvl + MN,              // K
        pqkvh + 2 * MN, pqkvl + 2 * MN,      // V
        pyh, pyl);

    // --- output projection --------------------------------------------------------
    const dim3 gg(N_EMBD / 128, MROWS / 128);
    gemm_out_mma<<<gg, 256, GEMM_SMEM>>>(pyh, pyl, bo, out);
}